// round 5
// baseline (speedup 1.0000x reference)
#include <cuda_runtime.h>
#include <cuda_bf16.h>
#include <math.h>
#include <stdint.h>

#define E_  8
#define H_  2048
#define I_  1024
#define I2_ 2048
#define L_  4
#define R_  16
#define T_  4096
#define P_  8192

#define KT1 2112     // H + L*R
#define KT2 1088     // I + L*R

// -------- scratch (device globals; allocation-free) --------
__device__ __nv_bfloat16 g_A1h[(size_t)P_*KT1], g_A1l[(size_t)P_*KT1];
__device__ __nv_bfloat16 g_B1h[(size_t)E_*I2_*KT1], g_B1l[(size_t)E_*I2_*KT1];
__device__ __nv_bfloat16 g_A2h[(size_t)P_*KT2], g_A2l[(size_t)P_*KT2];
__device__ __nv_bfloat16 g_B2h[(size_t)E_*H_*KT2], g_B2l[(size_t)E_*H_*KT2];
__device__ float g_D[(size_t)P_*H_];
__device__ int   g_list[P_], g_pos[P_], g_off[E_+1];

// -------- helpers --------
__device__ __forceinline__ uint32_t smem_u32(const void* p) {
    uint32_t a;
    asm("{ .reg .u64 t; cvta.to.shared.u64 t, %1; cvt.u32.u64 %0, t; }" : "=r"(a) : "l"(p));
    return a;
}
__device__ __forceinline__ uint32_t pk2(__nv_bfloat16 a, __nv_bfloat16 b) {
    __nv_bfloat162 t = __halves2bfloat162(a, b);
    return *reinterpret_cast<uint32_t*>(&t);
}
__device__ __forceinline__ void split2(float v, __nv_bfloat16& h, __nv_bfloat16& l) {
    h = __float2bfloat16(v);
    l = __float2bfloat16(v - __bfloat162float(h));
}
__device__ __forceinline__ void cp16(uint32_t dst, const void* src) {
    asm volatile("cp.async.cg.shared.global [%0], [%1], 16;" :: "r"(dst), "l"(src));
}
#define CP_COMMIT() asm volatile("cp.async.commit_group;" ::: "memory")
#define CP_WAIT2()  asm volatile("cp.async.wait_group 2;" ::: "memory")
#define CP_WAIT0()  asm volatile("cp.async.wait_group 0;" ::: "memory")

__device__ __forceinline__ void ldsm4(uint32_t* r, uint32_t addr) {
    asm volatile("ldmatrix.sync.aligned.m8n8.x4.shared.b16 {%0,%1,%2,%3}, [%4];"
        : "=r"(r[0]), "=r"(r[1]), "=r"(r[2]), "=r"(r[3]) : "r"(addr));
}
__device__ __forceinline__ void mma_bf16(float* d, const uint32_t* a, const uint32_t* b) {
    asm volatile(
        "mma.sync.aligned.m16n8k16.row.col.f32.bf16.bf16.f32 "
        "{%0,%1,%2,%3}, {%4,%5,%6,%7}, {%8,%9}, {%0,%1,%2,%3};"
        : "+f"(d[0]), "+f"(d[1]), "+f"(d[2]), "+f"(d[3])
        : "r"(a[0]), "r"(a[1]), "r"(a[2]), "r"(a[3]), "r"(b[0]), "r"(b[1]));
}
// swizzled smem offset for a [128 rows x 32 bf16] tile; r=row, c=16B chunk (0..3)
__device__ __forceinline__ uint32_t swz(int r, int c) {
    return (uint32_t)(r * 64 + ((c ^ ((r >> 1) & 3)) << 4));
}

// ============================================================
// routing: sort pairs by (expert, lora)
// ============================================================
__global__ void k_route(const int* __restrict__ topk_ids,
                        const int* __restrict__ lora_idx) {
    __shared__ int cnt[E_*L_], cur[E_*L_];
    int tid = threadIdx.x;
    if (tid < E_*L_) cnt[tid] = 0;
    __syncthreads();
    for (int p = tid; p < P_; p += blockDim.x)
        atomicAdd(&cnt[topk_ids[p]*L_ + lora_idx[p>>1]], 1);
    __syncthreads();
    if (tid == 0) {
        int acc = 0;
        for (int b = 0; b < E_*L_; b++) {
            if ((b & (L_-1)) == 0) g_off[b/L_] = acc;
            cur[b] = acc; acc += cnt[b];
        }
        g_off[E_] = acc;
    }
    __syncthreads();
    for (int p = tid; p < P_; p += blockDim.x) {
        int key = topk_ids[p]*L_ + lora_idx[p>>1];
        int pos = atomicAdd(&cur[key], 1);
        g_list[pos] = p;
        g_pos[p]    = pos;
    }
}

// ============================================================
// prep1
// ============================================================
__global__ __launch_bounds__(256) void k_prep1(
    const float* __restrict__ x, const float* __restrict__ gu_a,
    const int* __restrict__ topk_ids, const int* __restrict__ lora_idx) {
    int s = blockIdx.x, tid = threadIdx.x;
    int p = g_list[s], t = p >> 1;
    int e = topk_ids[p], l = lora_idx[t];
    const float4* x4 = (const float4*)(x + (size_t)t * H_);
    __nv_bfloat16* rh = g_A1h + (size_t)s * KT1;
    __nv_bfloat16* rl = g_A1l + (size_t)s * KT1;

    {
        float4 v0 = x4[tid*2], v1 = x4[tid*2+1];
        float vv[8] = {v0.x,v0.y,v0.z,v0.w,v1.x,v1.y,v1.z,v1.w};
        __nv_bfloat16 hh[8], ll[8];
        #pragma unroll
        for (int j = 0; j < 8; j++) split2(vv[j], hh[j], ll[j]);
        *(uint4*)(rh + tid*8) = make_uint4(pk2(hh[0],hh[1]),pk2(hh[2],hh[3]),pk2(hh[4],hh[5]),pk2(hh[6],hh[7]));
        *(uint4*)(rl + tid*8) = make_uint4(pk2(ll[0],ll[1]),pk2(ll[2],ll[3]),pk2(ll[4],ll[5]),pk2(ll[6],ll[7]));
    }
    __nv_bfloat16 z = __float2bfloat16(0.f);
    if (tid < L_*R_) { rh[H_+tid] = z; rl[H_+tid] = z; }
    __syncthreads();

    int lane = tid & 31, w = tid >> 5;
    const float4* a4 = (const float4*)(gu_a + (((size_t)l*E_ + e)*R_ + w) * H_);
    const float4* b4 = a4 + (size_t)8 * (H_/4);
    float sa = 0.f, sb = 0.f;
    for (int it = lane; it < H_/4; it += 32) {
        float4 xv = x4[it], av = a4[it], bv = b4[it];
        sa += xv.x*av.x + xv.y*av.y + xv.z*av.z + xv.w*av.w;
        sb += xv.x*bv.x + xv.y*bv.y + xv.z*bv.z + xv.w*bv.w;
    }
    #pragma unroll
    for (int o = 16; o; o >>= 1) {
        sa += __shfl_down_sync(0xffffffffu, sa, o);
        sb += __shfl_down_sync(0xffffffffu, sb, o);
    }
    if (lane == 0) {
        __nv_bfloat16 h, lo2;
        split2(sa, h, lo2); rh[H_+l*R_+w]   = h; rl[H_+l*R_+w]   = lo2;
        split2(sb, h, lo2); rh[H_+l*R_+w+8] = h; rl[H_+l*R_+w+8] = lo2;
    }
}

// ============================================================
// weight conversion
// ============================================================
__global__ __launch_bounds__(256) void k_convw1(
    const float* __restrict__ w13, const float* __restrict__ gu_b) {
    int rc = blockIdx.x, tid = threadIdx.x;
    int e = rc >> 11, c = rc & 2047;
    const float4* src = (const float4*)(w13 + (size_t)rc * H_);
    __nv_bfloat16* bh = g_B1h + (size_t)rc * KT1;
    __nv_bfloat16* bl = g_B1l + (size_t)rc * KT1;
    float4 v0 = src[tid*2], v1 = src[tid*2+1];
    float vv[8] = {v0.x,v0.y,v0.z,v0.w,v1.x,v1.y,v1.z,v1.w};
    __nv_bfloat16 hh[8], ll[8];
    #pragma unroll
    for (int j = 0; j < 8; j++) split2(vv[j], hh[j], ll[j]);
    *(uint4*)(bh + tid*8) = make_uint4(pk2(hh[0],hh[1]),pk2(hh[2],hh[3]),pk2(hh[4],hh[5]),pk2(hh[6],hh[7]));
    *(uint4*)(bl + tid*8) = make_uint4(pk2(ll[0],ll[1]),pk2(ll[2],ll[3]),pk2(ll[4],ll[5]),pk2(ll[6],ll[7]));
    if (tid < L_*R_) {
        int l = tid >> 4, r = tid & 15;
        float v = gu_b[(((size_t)l*E_ + e)*I2_ + c)*R_ + r];
        __nv_bfloat16 h, lo2; split2(v, h, lo2);
        bh[H_+tid] = h; bl[H_+tid] = lo2;
    }
}

__global__ __launch_bounds__(256) void k_convw2(
    const float* __restrict__ w2, const float* __restrict__ d_b) {
    int rc = blockIdx.x, tid = threadIdx.x;
    int e = rc >> 11, c = rc & 2047;
    const float4* src = (const float4*)(w2 + (size_t)rc * I_);
    __nv_bfloat16* bh = g_B2h + (size_t)rc * KT2;
    __nv_bfloat16* bl = g_B2l + (size_t)rc * KT2;
    float4 v0 = src[tid];
    float vv[4] = {v0.x,v0.y,v0.z,v0.w};
    __nv_bfloat16 hh[4], ll[4];
    #pragma unroll
    for (int j = 0; j < 4; j++) split2(vv[j], hh[j], ll[j]);
    *(uint2*)(bh + tid*4) = make_uint2(pk2(hh[0],hh[1]),pk2(hh[2],hh[3]));
    *(uint2*)(bl + tid*4) = make_uint2(pk2(ll[0],ll[1]),pk2(ll[2],ll[3]));
    if (tid < L_*R_) {
        int l = tid >> 4, r = tid & 15;
        float v = d_b[(((size_t)l*E_ + e)*H_ + c)*R_ + r];
        __nv_bfloat16 h, lo2; split2(v, h, lo2);
        bh[I_+tid] = h; bl[I_+tid] = lo2;
    }
}

// ============================================================
// prep2
// ============================================================
__global__ __launch_bounds__(256) void k_prep2(
    const float* __restrict__ d_a,
    const int* __restrict__ topk_ids, const int* __restrict__ lora_idx) {
    int s = blockIdx.x, tid = threadIdx.x;
    int p = g_list[s], t = p >> 1;
    int e = topk_ids[p], l = lora_idx[t];
    __nv_bfloat16* rh = g_A2h + (size_t)s * KT2;
    __nv_bfloat16* rl = g_A2l + (size_t)s * KT2;
    __nv_bfloat16 z = __float2bfloat16(0.f);
    if (tid < L_*R_) { rh[I_+tid] = z; rl[I_+tid] = z; }
    __syncthreads();

    int lane = tid & 31, w = tid >> 5;
    const float2* a2 = (const float2*)(d_a + (((size_t)l*E_ + e)*R_ + w) * I_);
    const float2* b2 = a2 + (size_t)8 * (I_/2);
    const __nv_bfloat162* h2 = (const __nv_bfloat162*)rh;
    const __nv_bfloat162* l2 = (const __nv_bfloat162*)rl;
    float sa = 0.f, sb = 0.f;
    for (int it = lane; it < I_/2; it += 32) {
        float2 fh = __bfloat1622float2(h2[it]);
        float2 fl = __bfloat1622float2(l2[it]);
        float a0 = fh.x + fl.x, a1 = fh.y + fl.y;
        float2 av = a2[it], bv = b2[it];
        sa += a0*av.x + a1*av.y;
        sb += a0*bv.x + a1*bv.y;
    }
    #pragma unroll
    for (int o = 16; o; o >>= 1) {
        sa += __shfl_down_sync(0xffffffffu, sa, o);
        sb += __shfl_down_sync(0xffffffffu, sb, o);
    }
    if (lane == 0) {
        __nv_bfloat16 h, lo2;
        split2(sa, h, lo2); rh[I_+l*R_+w]   = h; rl[I_+l*R_+w]   = lo2;
        split2(sb, h, lo2); rh[I_+l*R_+w+8] = h; rl[I_+l*R_+w+8] = lo2;
    }
}

// ============================================================
// mma.sync GEMM: CTA 128x128, 512 threads, 16 warps (32x32/warp),
// K chunks of 32, 4-stage cp.async. bf16 3-product split.
// ============================================================
#define STAGE 32768
#define SMEMB (4*STAGE)   // 131072

template<int GEMM>
__global__ __launch_bounds__(512, 1) void k_gemm_mma() {
    constexpr int KTOT = (GEMM == 1) ? KT1 : KT2;
    constexpr int NK   = KTOT / 32;
    const __nv_bfloat16* Ah = (GEMM == 1) ? g_A1h : g_A2h;
    const __nv_bfloat16* Al = (GEMM == 1) ? g_A1l : g_A2l;
    const __nv_bfloat16* Bh = (GEMM == 1) ? g_B1h : g_B2h;
    const __nv_bfloat16* Bl = (GEMM == 1) ? g_B1l : g_B2l;

    int e   = blockIdx.z;
    int off = g_off[e];
    int cnt = g_off[e+1] - off;
    int m0  = blockIdx.y * 128;
    if (m0 >= cnt) return;

    extern __shared__ char smem_raw[];
    uint32_t sbase = smem_u32(smem_raw);

    int tid = threadIdx.x;
    int lane = tid & 31, wid = tid >> 5;
    int wm = wid >> 2, wn = wid & 3;   // 4x4 warp grid, 32x32 each

    // ---- loader: one 16B chunk per thread per quarter ----
    int lr = tid >> 2, lc = tid & 3;
    int rA = m0 + lr; if (rA > cnt-1) rA = cnt-1;
    size_t ao = (size_t)(off + rA) * KTOT + lc*8;
    const __nv_bfloat16* gA[2] = { Ah + ao, Al + ao };
    int colB;
    if (GEMM == 1) colB = (lr < 64) ? (blockIdx.x*64 + lr) : (I_ + blockIdx.x*64 + lr - 64);
    else           colB = blockIdx.x*128 + lr;
    size_t bo = ((size_t)e * 2048 + colB) * KTOT + lc*8;
    const __nv_bfloat16* gB[2] = { Bh + bo, Bl + bo };
    uint32_t sOff = swz(lr, lc);

    auto issue = [&](int kt) {
        uint32_t st = sbase + (kt & 3) * STAGE;
        size_t kadd = (size_t)kt * 32;
        cp16(st +         sOff, gA[0] + kadd);
        cp16(st +  8192 + sOff, gA[1] + kadd);
        cp16(st + 16384 + sOff, gB[0] + kadd);
        cp16(st + 24576 + sOff, gB[1] + kadd);
    };

    // ---- ldmatrix lane geometry ----
    int aRow[2], bRow[2];
    #pragma unroll
    for (int i = 0; i < 2; i++) aRow[i] = wm*32 + i*16 + (lane & 15);
    int aC = (lane >> 4) & 1;
    #pragma unroll
    for (int g = 0; g < 2; g++) bRow[g] = wn*32 + g*16 + (lane & 7) + ((lane & 16) ? 8 : 0);
    int bC = (lane >> 3) & 1;

    float acc[2][4][4];
    #pragma unroll
    for (int i = 0; i < 2; i++)
        #pragma unroll
        for (int j = 0; j < 4; j++)
            #pragma unroll
            for (int q = 0; q < 4; q++) acc[i][j][q] = 0.f;

    issue(0); CP_COMMIT();
    issue(1); CP_COMMIT();
    issue(2); CP_COMMIT();

    for (int kt = 0; kt < NK; kt++) {
        CP_WAIT2();
        __syncthreads();
        if (kt + 3 < NK) issue(kt + 3);
        CP_COMMIT();

        uint32_t st = sbase + (kt & 3) * STAGE;
        #pragma unroll
        for (int h = 0; h < 2; h++) {
            uint32_t ah[2][4], al[2][4], bh[2][4], bl[2][4];
            #pragma unroll
            for (int i = 0; i < 2; i++) {
                uint32_t o = swz(aRow[i], 2*h + aC);
                ldsm4(ah[i], st + o);
                ldsm4(al[i], st + 8192 + o);
            }
            #pragma unroll
            for (int g = 0; g < 2; g++) {
                uint32_t o = swz(bRow[g], 2*h + bC);
                ldsm4(bh[g], st + 16384 + o);
                ldsm4(bl[g], st + 24576 + o);
            }
            #pragma unroll
            for (int i = 0; i < 2; i++)
                #pragma unroll
                for (int j = 0; j < 4; j++) {
                    const uint32_t* Bhj = &bh[j>>1][(j&1)*2];
                    const uint32_t* Blj = &bl[j>>1][(j&1)*2];
                    mma_bf16(acc[i][j], ah[i], Bhj);
                    mma_bf16(acc[i][j], ah[i], Blj);
                    mma_bf16(acc[i][j], al[i], Bhj);
                }
        }
    }
    CP_WAIT0();
    __syncthreads();

    if constexpr (GEMM == 1) {
        float* ex = reinterpret_cast<float*>(smem_raw);   // [128][132] fp32
        #pragma unroll
        for (int i = 0; i < 2; i++)
            #pragma unroll
            for (int j = 0; j < 4; j++) {
                int r0 = wm*32 + i*16 + (lane >> 2);
                int c  = wn*32 + j*8 + (lane & 3)*2;
                ex[r0*132 + c]       = acc[i][j][0];
                ex[r0*132 + c + 1]   = acc[i][j][1];
                ex[(r0+8)*132 + c]   = acc[i][j][2];
                ex[(r0+8)*132 + c+1] = acc[i][j][3];
            }
        __syncthreads();
        int m = tid >> 2, q = tid & 3;   // row, 16-col quarter
        if (m0 + m < cnt) {
            size_t srow = (size_t)(off + m0 + m);
            __nv_bfloat16* dh = g_A2h + srow * KT2 + blockIdx.x*64 + q*16;
            __nv_bfloat16* dl = g_A2l + srow * KT2 + blockIdx.x*64 + q*16;
            const float* gr = ex + m*132 + q*16;
            uint32_t hw[8], lw[8];
            #pragma unroll
            for (int u = 0; u < 8; u++) {
                float g0 = gr[u*2], g1 = gr[u*2 + 1];
                float u0 = gr[64 + u*2], u1 = gr[64 + u*2 + 1];
                float a0 = u0 * g0 / (1.f + expf(-g0));
                float a1 = u1 * g1 / (1.f + expf(-g1));
                __nv_bfloat16 h0, l0, h1, l1;
                split2(a0, h0, l0); split2(a1, h1, l1);
                hw[u] = pk2(h0, h1); lw[u] = pk2(l0, l1);
            }
            *(uint4*)(dh)     = make_uint4(hw[0], hw[1], hw[2], hw[3]);
            *(uint4*)(dh + 8) = make_uint4(hw[4], hw[5], hw[6], hw[7]);
            *(uint4*)(dl)     = make_uint4(lw[0], lw[1], lw[2], lw[3]);
            *(uint4*)(dl + 8) = make_uint4(lw[4], lw[5], lw[6], lw[7]);
        }
    } else {
        int c0 = blockIdx.x * 128;
        #pragma unroll
        for (int i = 0; i < 2; i++) {
            int r0 = m0 + wm*32 + i*16 + (lane >> 2);
            #pragma unroll
            for (int j = 0; j < 4; j++) {
                int c = c0 + wn*32 + j*8 + (lane & 3)*2;
                if (r0 < cnt)
                    *(float2*)(g_D + (size_t)(off + r0) * H_ + c) =
                        make_float2(acc[i][j][0], acc[i][j][1]);
                if (r0 + 8 < cnt)
                    *(float2*)(g_D + (size_t)(off + r0 + 8) * H_ + c) =
                        make_float2(acc[i][j][2], acc[i][j][3]);
            }
        }
    }
}

// ============================================================
// combine
// ============================================================
__global__ __launch_bounds__(256) void k_combine(
    const float* __restrict__ tw, float* __restrict__ out) {
    int idx = blockIdx.x * 256 + threadIdx.x;
    int t = idx >> 9, h4 = idx & 511;
    float w0 = tw[2*t], w1 = tw[2*t+1];
    const float4* d0 = (const float4*)(g_D + (size_t)g_pos[2*t]   * H_);
    const float4* d1 = (const float4*)(g_D + (size_t)g_pos[2*t+1] * H_);
    float4 a = d0[h4], b = d1[h4], o;
    o.x = w0*a.x + w1*b.x; o.y = w0*a.y + w1*b.y;
    o.z = w0*a.z + w1*b.z; o.w = w0*a.w + w1*b.w;
    ((float4*)out)[idx] = o;
}

// ============================================================
extern "C" void kernel_launch(void* const* d_in, const int* in_sizes, int n_in,
                              void* d_out, int out_size) {
    const float* x    = (const float*)d_in[0];
    const float* tw   = (const float*)d_in[1];
    const float* w13  = (const float*)d_in[2];
    const float* w2   = (const float*)d_in[3];
    const float* gu_a = (const float*)d_in[4];
    const float* gu_b = (const float*)d_in[5];
    const float* da   = (const float*)d_in[6];
    const float* db   = (const float*)d_in[7];
    const int*   ids  = (const int*)d_in[8];
    const int*   lidx = (const int*)d_in[9];
    float* out = (float*)d_out;

    cudaFuncSetAttribute(k_gemm_mma<1>, cudaFuncAttributeMaxDynamicSharedMemorySize, SMEMB);
    cudaFuncSetAttribute(k_gemm_mma<2>, cudaFuncAttributeMaxDynamicSharedMemorySize, SMEMB);

    // order chosen so k_gemm_mma<1> is launch #4 (ncu captures it)
    k_route  <<<1, 256>>>(ids, lidx);
    k_convw1 <<<E_*I2_, 256>>>(w13, gu_b);
    k_prep1  <<<P_, 256>>>(x, gu_a, ids, lidx);
    k_gemm_mma<1><<<dim3(16, 64, E_), 512, SMEMB>>>();
    k_convw2 <<<E_*H_,  256>>>(w2, db);
    k_prep2  <<<P_, 256>>>(da, ids, lidx);
    k_gemm_mma<2><<<dim3(16, 64, E_), 512, SMEMB>>>();
    k_combine<<<(T_*H_/4)/256, 256>>>(tw, out);
}

// round 6
// speedup vs baseline: 1.0184x; 1.0184x over previous
#include <cuda_runtime.h>
#include <cuda_bf16.h>
#include <math.h>
#include <stdint.h>

#define E_  8
#define H_  2048
#define I_  1024
#define I2_ 2048
#define L_  4
#define R_  16
#define T_  4096
#define P_  8192

#define KT1 2112     // H + L*R  (= 33*64)
#define KT2 1088     // I + L*R  (= 17*64)

// -------- scratch (device globals; allocation-free) --------
__device__ __nv_bfloat16 g_A1h[(size_t)P_*KT1], g_A1l[(size_t)P_*KT1];
__device__ __nv_bfloat16 g_B1h[(size_t)E_*I2_*KT1], g_B1l[(size_t)E_*I2_*KT1];
__device__ __nv_bfloat16 g_A2h[(size_t)P_*KT2], g_A2l[(size_t)P_*KT2];
__device__ __nv_bfloat16 g_B2h[(size_t)E_*H_*KT2], g_B2l[(size_t)E_*H_*KT2];
__device__ float g_D[(size_t)P_*H_];
__device__ int   g_list[P_], g_pos[P_], g_off[E_+1];

// -------- helpers --------
__device__ __forceinline__ uint32_t smem_u32(const void* p) {
    uint32_t a;
    asm("{ .reg .u64 t; cvta.to.shared.u64 t, %1; cvt.u32.u64 %0, t; }" : "=r"(a) : "l"(p));
    return a;
}
__device__ __forceinline__ uint32_t pk2(__nv_bfloat16 a, __nv_bfloat16 b) {
    __nv_bfloat162 t = __halves2bfloat162(a, b);
    return *reinterpret_cast<uint32_t*>(&t);
}
__device__ __forceinline__ void split2(float v, __nv_bfloat16& h, __nv_bfloat16& l) {
    h = __float2bfloat16(v);
    l = __float2bfloat16(v - __bfloat162float(h));
}
__device__ __forceinline__ void cp16(uint32_t dst, const void* src) {
    asm volatile("cp.async.cg.shared.global [%0], [%1], 16;" :: "r"(dst), "l"(src));
}
#define CP_COMMIT() asm volatile("cp.async.commit_group;" ::: "memory")
#define CP_WAIT1()  asm volatile("cp.async.wait_group 1;" ::: "memory")
#define CP_WAIT0()  asm volatile("cp.async.wait_group 0;" ::: "memory")

__device__ __forceinline__ void ldsm4(uint32_t* r, uint32_t addr) {
    asm volatile("ldmatrix.sync.aligned.m8n8.x4.shared.b16 {%0,%1,%2,%3}, [%4];"
        : "=r"(r[0]), "=r"(r[1]), "=r"(r[2]), "=r"(r[3]) : "r"(addr));
}
__device__ __forceinline__ void mma_bf16(float* d, const uint32_t* a, const uint32_t* b) {
    asm volatile(
        "mma.sync.aligned.m16n8k16.row.col.f32.bf16.bf16.f32 "
        "{%0,%1,%2,%3}, {%4,%5,%6,%7}, {%8,%9}, {%0,%1,%2,%3};"
        : "+f"(d[0]), "+f"(d[1]), "+f"(d[2]), "+f"(d[3])
        : "r"(a[0]), "r"(a[1]), "r"(a[2]), "r"(a[3]), "r"(b[0]), "r"(b[1]));
}
// stage tiles are [128 rows x 64 bf16] = row stride 128B, 8x 16B chunks/row
__device__ __forceinline__ uint32_t swz64(int r, int c) {
    return (uint32_t)(r * 128 + ((c ^ (r & 7)) << 4));
}

// ============================================================
// routing: sort pairs by (expert, lora)
// ============================================================
__global__ void k_route(const int* __restrict__ topk_ids,
                        const int* __restrict__ lora_idx) {
    __shared__ int cnt[E_*L_], cur[E_*L_];
    int tid = threadIdx.x;
    if (tid < E_*L_) cnt[tid] = 0;
    __syncthreads();
    for (int p = tid; p < P_; p += blockDim.x)
        atomicAdd(&cnt[topk_ids[p]*L_ + lora_idx[p>>1]], 1);
    __syncthreads();
    if (tid == 0) {
        int acc = 0;
        for (int b = 0; b < E_*L_; b++) {
            if ((b & (L_-1)) == 0) g_off[b/L_] = acc;
            cur[b] = acc; acc += cnt[b];
        }
        g_off[E_] = acc;
    }
    __syncthreads();
    for (int p = tid; p < P_; p += blockDim.x) {
        int key = topk_ids[p]*L_ + lora_idx[p>>1];
        int pos = atomicAdd(&cur[key], 1);
        g_list[pos] = p;
        g_pos[p]    = pos;
    }
}

// ============================================================
// prep1
// ============================================================
__global__ __launch_bounds__(256) void k_prep1(
    const float* __restrict__ x, const float* __restrict__ gu_a,
    const int* __restrict__ topk_ids, const int* __restrict__ lora_idx) {
    int s = blockIdx.x, tid = threadIdx.x;
    int p = g_list[s], t = p >> 1;
    int e = topk_ids[p], l = lora_idx[t];
    const float4* x4 = (const float4*)(x + (size_t)t * H_);
    __nv_bfloat16* rh = g_A1h + (size_t)s * KT1;
    __nv_bfloat16* rl = g_A1l + (size_t)s * KT1;

    {
        float4 v0 = x4[tid*2], v1 = x4[tid*2+1];
        float vv[8] = {v0.x,v0.y,v0.z,v0.w,v1.x,v1.y,v1.z,v1.w};
        __nv_bfloat16 hh[8], ll[8];
        #pragma unroll
        for (int j = 0; j < 8; j++) split2(vv[j], hh[j], ll[j]);
        *(uint4*)(rh + tid*8) = make_uint4(pk2(hh[0],hh[1]),pk2(hh[2],hh[3]),pk2(hh[4],hh[5]),pk2(hh[6],hh[7]));
        *(uint4*)(rl + tid*8) = make_uint4(pk2(ll[0],ll[1]),pk2(ll[2],ll[3]),pk2(ll[4],ll[5]),pk2(ll[6],ll[7]));
    }
    __nv_bfloat16 z = __float2bfloat16(0.f);
    if (tid < L_*R_) { rh[H_+tid] = z; rl[H_+tid] = z; }
    __syncthreads();

    int lane = tid & 31, w = tid >> 5;
    const float4* a4 = (const float4*)(gu_a + (((size_t)l*E_ + e)*R_ + w) * H_);
    const float4* b4 = a4 + (size_t)8 * (H_/4);
    float sa = 0.f, sb = 0.f;
    for (int it = lane; it < H_/4; it += 32) {
        float4 xv = x4[it], av = a4[it], bv = b4[it];
        sa += xv.x*av.x + xv.y*av.y + xv.z*av.z + xv.w*av.w;
        sb += xv.x*bv.x + xv.y*bv.y + xv.z*bv.z + xv.w*bv.w;
    }
    #pragma unroll
    for (int o = 16; o; o >>= 1) {
        sa += __shfl_down_sync(0xffffffffu, sa, o);
        sb += __shfl_down_sync(0xffffffffu, sb, o);
    }
    if (lane == 0) {
        __nv_bfloat16 h, lo2;
        split2(sa, h, lo2); rh[H_+l*R_+w]   = h; rl[H_+l*R_+w]   = lo2;
        split2(sb, h, lo2); rh[H_+l*R_+w+8] = h; rl[H_+l*R_+w+8] = lo2;
    }
}

// ============================================================
// weight conversion
// ============================================================
__global__ __launch_bounds__(256) void k_convw1(
    const float* __restrict__ w13, const float* __restrict__ gu_b) {
    int rc = blockIdx.x, tid = threadIdx.x;
    int e = rc >> 11, c = rc & 2047;
    const float4* src = (const float4*)(w13 + (size_t)rc * H_);
    __nv_bfloat16* bh = g_B1h + (size_t)rc * KT1;
    __nv_bfloat16* bl = g_B1l + (size_t)rc * KT1;
    float4 v0 = src[tid*2], v1 = src[tid*2+1];
    float vv[8] = {v0.x,v0.y,v0.z,v0.w,v1.x,v1.y,v1.z,v1.w};
    __nv_bfloat16 hh[8], ll[8];
    #pragma unroll
    for (int j = 0; j < 8; j++) split2(vv[j], hh[j], ll[j]);
    *(uint4*)(bh + tid*8) = make_uint4(pk2(hh[0],hh[1]),pk2(hh[2],hh[3]),pk2(hh[4],hh[5]),pk2(hh[6],hh[7]));
    *(uint4*)(bl + tid*8) = make_uint4(pk2(ll[0],ll[1]),pk2(ll[2],ll[3]),pk2(ll[4],ll[5]),pk2(ll[6],ll[7]));
    if (tid < L_*R_) {
        int l = tid >> 4, r = tid & 15;
        float v = gu_b[(((size_t)l*E_ + e)*I2_ + c)*R_ + r];
        __nv_bfloat16 h, lo2; split2(v, h, lo2);
        bh[H_+tid] = h; bl[H_+tid] = lo2;
    }
}

__global__ __launch_bounds__(256) void k_convw2(
    const float* __restrict__ w2, const float* __restrict__ d_b) {
    int rc = blockIdx.x, tid = threadIdx.x;
    int e = rc >> 11, c = rc & 2047;
    const float4* src = (const float4*)(w2 + (size_t)rc * I_);
    __nv_bfloat16* bh = g_B2h + (size_t)rc * KT2;
    __nv_bfloat16* bl = g_B2l + (size_t)rc * KT2;
    float4 v0 = src[tid];
    float vv[4] = {v0.x,v0.y,v0.z,v0.w};
    __nv_bfloat16 hh[4], ll[4];
    #pragma unroll
    for (int j = 0; j < 4; j++) split2(vv[j], hh[j], ll[j]);
    *(uint2*)(bh + tid*4) = make_uint2(pk2(hh[0],hh[1]),pk2(hh[2],hh[3]));
    *(uint2*)(bl + tid*4) = make_uint2(pk2(ll[0],ll[1]),pk2(ll[2],ll[3]));
    if (tid < L_*R_) {
        int l = tid >> 4, r = tid & 15;
        float v = d_b[(((size_t)l*E_ + e)*H_ + c)*R_ + r];
        __nv_bfloat16 h, lo2; split2(v, h, lo2);
        bh[I_+tid] = h; bl[I_+tid] = lo2;
    }
}

// ============================================================
// prep2
// ============================================================
__global__ __launch_bounds__(256) void k_prep2(
    const float* __restrict__ d_a,
    const int* __restrict__ topk_ids, const int* __restrict__ lora_idx) {
    int s = blockIdx.x, tid = threadIdx.x;
    int p = g_list[s], t = p >> 1;
    int e = topk_ids[p], l = lora_idx[t];
    __nv_bfloat16* rh = g_A2h + (size_t)s * KT2;
    __nv_bfloat16* rl = g_A2l + (size_t)s * KT2;
    __nv_bfloat16 z = __float2bfloat16(0.f);
    if (tid < L_*R_) { rh[I_+tid] = z; rl[I_+tid] = z; }
    __syncthreads();

    int lane = tid & 31, w = tid >> 5;
    const float2* a2 = (const float2*)(d_a + (((size_t)l*E_ + e)*R_ + w) * I_);
    const float2* b2 = a2 + (size_t)8 * (I_/2);
    const __nv_bfloat162* h2 = (const __nv_bfloat162*)rh;
    const __nv_bfloat162* l2 = (const __nv_bfloat162*)rl;
    float sa = 0.f, sb = 0.f;
    for (int it = lane; it < I_/2; it += 32) {
        float2 fh = __bfloat1622float2(h2[it]);
        float2 fl = __bfloat1622float2(l2[it]);
        float a0 = fh.x + fl.x, a1 = fh.y + fl.y;
        float2 av = a2[it], bv = b2[it];
        sa += a0*av.x + a1*av.y;
        sb += a0*bv.x + a1*bv.y;
    }
    #pragma unroll
    for (int o = 16; o; o >>= 1) {
        sa += __shfl_down_sync(0xffffffffu, sa, o);
        sb += __shfl_down_sync(0xffffffffu, sb, o);
    }
    if (lane == 0) {
        __nv_bfloat16 h, lo2;
        split2(sa, h, lo2); rh[I_+l*R_+w]   = h; rl[I_+l*R_+w]   = lo2;
        split2(sb, h, lo2); rh[I_+l*R_+w+8] = h; rl[I_+l*R_+w+8] = lo2;
    }
}

// ============================================================
// mma.sync GEMM: CTA 128x128, 512 threads / 16 warps (32x32 each).
// K chunk 64 per stage, 3 stages x 64KB, fragments double-buffered
// across the 4 k16 sub-chunks. bf16 3-product split (hh+hl+lh).
// ============================================================
#define STAGE 65536
#define SMEMB (3*STAGE)   // 196608

template<int GEMM>
__global__ __launch_bounds__(512, 1) void k_gemm_mma() {
    constexpr int KTOT = (GEMM == 1) ? KT1 : KT2;
    constexpr int NK   = KTOT / 64;
    const __nv_bfloat16* Ah = (GEMM == 1) ? g_A1h : g_A2h;
    const __nv_bfloat16* Al = (GEMM == 1) ? g_A1l : g_A2l;
    const __nv_bfloat16* Bh = (GEMM == 1) ? g_B1h : g_B2h;
    const __nv_bfloat16* Bl = (GEMM == 1) ? g_B1l : g_B2l;

    int e   = blockIdx.z;
    int off = g_off[e];
    int cnt = g_off[e+1] - off;
    int m0  = blockIdx.y * 128;
    if (m0 >= cnt) return;

    extern __shared__ char smem_raw[];
    uint32_t sbase = smem_u32(smem_raw);

    int tid = threadIdx.x;
    int lane = tid & 31, wid = tid >> 5;
    int wm = wid >> 2, wn = wid & 3;   // 4x4 warp grid, 32x32 each

    // ---- loader: each thread loads 2 chunks per matrix per stage ----
    int lr = tid >> 2, lc = tid & 3;   // row 0..127, base chunk 0..3 (+4)
    int rA = m0 + lr; if (rA > cnt-1) rA = cnt-1;
    size_t ao = (size_t)(off + rA) * KTOT;
    const __nv_bfloat16* gA[2] = { Ah + ao, Al + ao };
    int colB;
    if (GEMM == 1) colB = (lr < 64) ? (blockIdx.x*64 + lr) : (I_ + blockIdx.x*64 + lr - 64);
    else           colB = blockIdx.x*128 + lr;
    size_t bo = ((size_t)e * 2048 + colB) * KTOT;
    const __nv_bfloat16* gB[2] = { Bh + bo, Bl + bo };
    uint32_t s0 = swz64(lr, lc), s1 = swz64(lr, lc + 4);

    auto issue = [&](int kt) {
        uint32_t st = sbase + (kt % 3) * STAGE;
        size_t k0 = (size_t)kt * 64 + lc*8;
        size_t k1 = k0 + 32;
        cp16(st +         s0, gA[0] + k0);  cp16(st +         s1, gA[0] + k1);
        cp16(st + 16384 + s0, gA[1] + k0);  cp16(st + 16384 + s1, gA[1] + k1);
        cp16(st + 32768 + s0, gB[0] + k0);  cp16(st + 32768 + s1, gB[0] + k1);
        cp16(st + 49152 + s0, gB[1] + k0);  cp16(st + 49152 + s1, gB[1] + k1);
    };

    // ---- ldmatrix lane geometry ----
    int aRow[2], bRow[2];
    #pragma unroll
    for (int i = 0; i < 2; i++) aRow[i] = wm*32 + i*16 + (lane & 15);
    int aC = (lane >> 4) & 1;
    #pragma unroll
    for (int g = 0; g < 2; g++) bRow[g] = wn*32 + g*16 + (lane & 7) + ((lane & 16) ? 8 : 0);
    int bC = (lane >> 3) & 1;

    float acc[2][4][4];
    #pragma unroll
    for (int i = 0; i < 2; i++)
        #pragma unroll
        for (int j = 0; j < 4; j++)
            #pragma unroll
            for (int q = 0; q < 4; q++) acc[i][j][q] = 0.f;

    uint32_t ah[2][2][4], al[2][2][4], bh[2][2][4], bl[2][2][4];  // [buf][i/g][4]

    issue(0); CP_COMMIT();
    issue(1); CP_COMMIT();

    for (int kt = 0; kt < NK; kt++) {
        CP_WAIT1();
        __syncthreads();
        if (kt + 2 < NK) issue(kt + 2);
        CP_COMMIT();

        uint32_t st = sbase + (kt % 3) * STAGE;
        // prime sub-chunk 0
        #pragma unroll
        for (int i = 0; i < 2; i++) {
            uint32_t o = swz64(aRow[i], aC);
            ldsm4(ah[0][i], st + o);
            ldsm4(al[0][i], st + 16384 + o);
        }
        #pragma unroll
        for (int g = 0; g < 2; g++) {
            uint32_t o = swz64(bRow[g], bC);
            ldsm4(bh[0][g], st + 32768 + o);
            ldsm4(bl[0][g], st + 49152 + o);
        }
        #pragma unroll
        for (int sub = 0; sub < 4; sub++) {
            int buf = sub & 1;
            if (sub < 3) {
                int nb = buf ^ 1;
                #pragma unroll
                for (int i = 0; i < 2; i++) {
                    uint32_t o = swz64(aRow[i], 2*(sub+1) + aC);
                    ldsm4(ah[nb][i], st + o);
                    ldsm4(al[nb][i], st + 16384 + o);
                }
                #pragma unroll
                for (int g = 0; g < 2; g++) {
                    uint32_t o = swz64(bRow[g], 2*(sub+1) + bC);
                    ldsm4(bh[nb][g], st + 32768 + o);
                    ldsm4(bl[nb][g], st + 49152 + o);
                }
            }
            #pragma unroll
            for (int i = 0; i < 2; i++)
                #pragma unroll
                for (int j = 0; j < 4; j++) {
                    const uint32_t* Bhj = &bh[buf][j>>1][(j&1)*2];
                    const uint32_t* Blj = &bl[buf][j>>1][(j&1)*2];
                    mma_bf16(acc[i][j], ah[buf][i], Bhj);
                    mma_bf16(acc[i][j], ah[buf][i], Blj);
                    mma_bf16(acc[i][j], al[buf][i], Bhj);
                }
        }
    }
    CP_WAIT0();
    __syncthreads();

    if constexpr (GEMM == 1) {
        float* ex = reinterpret_cast<float*>(smem_raw);   // [128][132] fp32
        #pragma unroll
        for (int i = 0; i < 2; i++)
            #pragma unroll
            for (int j = 0; j < 4; j++) {
                int r0 = wm*32 + i*16 + (lane >> 2);
                int c  = wn*32 + j*8 + (lane & 3)*2;
                ex[r0*132 + c]       = acc[i][j][0];
                ex[r0*132 + c + 1]   = acc[i][j][1];
                ex[(r0+8)*132 + c]   = acc[i][j][2];
                ex[(r0+8)*132 + c+1] = acc[i][j][3];
            }
        __syncthreads();
        int m = tid >> 2, q = tid & 3;
        if (m0 + m < cnt) {
            size_t srow = (size_t)(off + m0 + m);
            __nv_bfloat16* dh = g_A2h + srow * KT2 + blockIdx.x*64 + q*16;
            __nv_bfloat16* dl = g_A2l + srow * KT2 + blockIdx.x*64 + q*16;
            const float* gr = ex + m*132 + q*16;
            uint32_t hw[8], lw[8];
            #pragma unroll
            for (int u = 0; u < 8; u++) {
                float g0 = gr[u*2], g1 = gr[u*2 + 1];
                float u0 = gr[64 + u*2], u1 = gr[64 + u*2 + 1];
                float a0 = u0 * g0 / (1.f + expf(-g0));
                float a1 = u1 * g1 / (1.f + expf(-g1));
                __nv_bfloat16 h0, l0, h1, l1;
                split2(a0, h0, l0); split2(a1, h1, l1);
                hw[u] = pk2(h0, h1); lw[u] = pk2(l0, l1);
            }
            *(uint4*)(dh)     = make_uint4(hw[0], hw[1], hw[2], hw[3]);
            *(uint4*)(dh + 8) = make_uint4(hw[4], hw[5], hw[6], hw[7]);
            *(uint4*)(dl)     = make_uint4(lw[0], lw[1], lw[2], lw[3]);
            *(uint4*)(dl + 8) = make_uint4(lw[4], lw[5], lw[6], lw[7]);
        }
    } else {
        int c0 = blockIdx.x * 128;
        #pragma unroll
        for (int i = 0; i < 2; i++) {
            int r0 = m0 + wm*32 + i*16 + (lane >> 2);
            #pragma unroll
            for (int j = 0; j < 4; j++) {
                int c = c0 + wn*32 + j*8 + (lane & 3)*2;
                if (r0 < cnt)
                    *(float2*)(g_D + (size_t)(off + r0) * H_ + c) =
                        make_float2(acc[i][j][0], acc[i][j][1]);
                if (r0 + 8 < cnt)
                    *(float2*)(g_D + (size_t)(off + r0 + 8) * H_ + c) =
                        make_float2(acc[i][j][2], acc[i][j][3]);
            }
        }
    }
}

// ============================================================
// combine
// ============================================================
__global__ __launch_bounds__(256) void k_combine(
    const float* __restrict__ tw, float* __restrict__ out) {
    int idx = blockIdx.x * 256 + threadIdx.x;
    int t = idx >> 9, h4 = idx & 511;
    float w0 = tw[2*t], w1 = tw[2*t+1];
    const float4* d0 = (const float4*)(g_D + (size_t)g_pos[2*t]   * H_);
    const float4* d1 = (const float4*)(g_D + (size_t)g_pos[2*t+1] * H_);
    float4 a = d0[h4], b = d1[h4], o;
    o.x = w0*a.x + w1*b.x; o.y = w0*a.y + w1*b.y;
    o.z = w0*a.z + w1*b.z; o.w = w0*a.w + w1*b.w;
    ((float4*)out)[idx] = o;
}

// ============================================================
extern "C" void kernel_launch(void* const* d_in, const int* in_sizes, int n_in,
                              void* d_out, int out_size) {
    const float* x    = (const float*)d_in[0];
    const float* tw   = (const float*)d_in[1];
    const float* w13  = (const float*)d_in[2];
    const float* w2   = (const float*)d_in[3];
    const float* gu_a = (const float*)d_in[4];
    const float* gu_b = (const float*)d_in[5];
    const float* da   = (const float*)d_in[6];
    const float* db   = (const float*)d_in[7];
    const int*   ids  = (const int*)d_in[8];
    const int*   lidx = (const int*)d_in[9];
    float* out = (float*)d_out;

    cudaFuncSetAttribute(k_gemm_mma<1>, cudaFuncAttributeMaxDynamicSharedMemorySize, SMEMB);
    cudaFuncSetAttribute(k_gemm_mma<2>, cudaFuncAttributeMaxDynamicSharedMemorySize, SMEMB);

    // order chosen so k_gemm_mma<1> is launch #4 (ncu captures it)
    k_route  <<<1, 256>>>(ids, lidx);
    k_convw1 <<<E_*I2_, 256>>>(w13, gu_b);
    k_prep1  <<<P_, 256>>>(x, gu_a, ids, lidx);
    k_gemm_mma<1><<<dim3(16, 64, E_), 512, SMEMB>>>();
    k_convw2 <<<E_*H_,  256>>>(w2, db);
    k_prep2  <<<P_, 256>>>(da, ids, lidx);
    k_gemm_mma<2><<<dim3(16, 64, E_), 512, SMEMB>>>();
    k_combine<<<(T_*H_/4)/256, 256>>>(tw, out);
}

// round 7
// speedup vs baseline: 1.0734x; 1.0540x over previous
#include <cuda_runtime.h>
#include <cuda_bf16.h>
#include <math.h>
#include <stdint.h>

#define E_  8
#define H_  2048
#define I_  1024
#define I2_ 2048
#define L_  4
#define R_  16
#define T_  4096
#define P_  8192

#define KT1 2112     // H + L*R
#define KT2 1088     // I + L*R

// -------- scratch (device globals; allocation-free) --------
__device__ __nv_bfloat16 g_A1h[(size_t)P_*KT1], g_A1l[(size_t)P_*KT1];
__device__ __nv_bfloat16 g_B1h[(size_t)E_*I2_*KT1], g_B1l[(size_t)E_*I2_*KT1];
__device__ __nv_bfloat16 g_A2h[(size_t)P_*KT2], g_A2l[(size_t)P_*KT2];
__device__ __nv_bfloat16 g_B2h[(size_t)E_*H_*KT2], g_B2l[(size_t)E_*H_*KT2];
__device__ float g_D[(size_t)P_*H_];
__device__ int   g_list[P_], g_pos[P_], g_off[E_+1];

// -------- helpers --------
__device__ __forceinline__ uint32_t smem_u32(const void* p) {
    uint32_t a;
    asm("{ .reg .u64 t; cvta.to.shared.u64 t, %1; cvt.u32.u64 %0, t; }" : "=r"(a) : "l"(p));
    return a;
}
__device__ __forceinline__ uint32_t pk2(__nv_bfloat16 a, __nv_bfloat16 b) {
    __nv_bfloat162 t = __halves2bfloat162(a, b);
    return *reinterpret_cast<uint32_t*>(&t);
}
__device__ __forceinline__ void split2(float v, __nv_bfloat16& h, __nv_bfloat16& l) {
    h = __float2bfloat16(v);
    l = __float2bfloat16(v - __bfloat162float(h));
}
__device__ __forceinline__ void cp16(uint32_t dst, const void* src) {
    asm volatile("cp.async.cg.shared.global [%0], [%1], 16;" :: "r"(dst), "l"(src));
}
#define CP_COMMIT() asm volatile("cp.async.commit_group;" ::: "memory")
#define CP_WAIT1()  asm volatile("cp.async.wait_group 1;" ::: "memory")
#define CP_WAIT0()  asm volatile("cp.async.wait_group 0;" ::: "memory")

__device__ __forceinline__ void ldsm4(uint32_t* r, uint32_t addr) {
    asm volatile("ldmatrix.sync.aligned.m8n8.x4.shared.b16 {%0,%1,%2,%3}, [%4];"
        : "=r"(r[0]), "=r"(r[1]), "=r"(r[2]), "=r"(r[3]) : "r"(addr));
}
__device__ __forceinline__ void mma_bf16(float* d, const uint32_t* a, const uint32_t* b) {
    asm volatile(
        "mma.sync.aligned.m16n8k16.row.col.f32.bf16.bf16.f32 "
        "{%0,%1,%2,%3}, {%4,%5,%6,%7}, {%8,%9}, {%0,%1,%2,%3};"
        : "+f"(d[0]), "+f"(d[1]), "+f"(d[2]), "+f"(d[3])
        : "r"(a[0]), "r"(a[1]), "r"(a[2]), "r"(a[3]), "r"(b[0]), "r"(b[1]));
}
// [rows x 32 bf16] tile, row stride 64B, 4x 16B chunks/row
__device__ __forceinline__ uint32_t swz32(int r, int c) {
    return (uint32_t)(r * 64 + ((c ^ ((r >> 1) & 3)) << 4));
}

// ============================================================
// routing: sort pairs by (expert, lora)
// ============================================================
__global__ void k_route(const int* __restrict__ topk_ids,
                        const int* __restrict__ lora_idx) {
    __shared__ int cnt[E_*L_], cur[E_*L_];
    int tid = threadIdx.x;
    if (tid < E_*L_) cnt[tid] = 0;
    __syncthreads();
    for (int p = tid; p < P_; p += blockDim.x)
        atomicAdd(&cnt[topk_ids[p]*L_ + lora_idx[p>>1]], 1);
    __syncthreads();
    if (tid == 0) {
        int acc = 0;
        for (int b = 0; b < E_*L_; b++) {
            if ((b & (L_-1)) == 0) g_off[b/L_] = acc;
            cur[b] = acc; acc += cnt[b];
        }
        g_off[E_] = acc;
    }
    __syncthreads();
    for (int p = tid; p < P_; p += blockDim.x) {
        int key = topk_ids[p]*L_ + lora_idx[p>>1];
        int pos = atomicAdd(&cur[key], 1);
        g_list[pos] = p;
        g_pos[p]    = pos;
    }
}

// ============================================================
// prep1
// ============================================================
__global__ __launch_bounds__(256) void k_prep1(
    const float* __restrict__ x, const float* __restrict__ gu_a,
    const int* __restrict__ topk_ids, const int* __restrict__ lora_idx) {
    int s = blockIdx.x, tid = threadIdx.x;
    int p = g_list[s], t = p >> 1;
    int e = topk_ids[p], l = lora_idx[t];
    const float4* x4 = (const float4*)(x + (size_t)t * H_);
    __nv_bfloat16* rh = g_A1h + (size_t)s * KT1;
    __nv_bfloat16* rl = g_A1l + (size_t)s * KT1;

    {
        float4 v0 = x4[tid*2], v1 = x4[tid*2+1];
        float vv[8] = {v0.x,v0.y,v0.z,v0.w,v1.x,v1.y,v1.z,v1.w};
        __nv_bfloat16 hh[8], ll[8];
        #pragma unroll
        for (int j = 0; j < 8; j++) split2(vv[j], hh[j], ll[j]);
        *(uint4*)(rh + tid*8) = make_uint4(pk2(hh[0],hh[1]),pk2(hh[2],hh[3]),pk2(hh[4],hh[5]),pk2(hh[6],hh[7]));
        *(uint4*)(rl + tid*8) = make_uint4(pk2(ll[0],ll[1]),pk2(ll[2],ll[3]),pk2(ll[4],ll[5]),pk2(ll[6],ll[7]));
    }
    __nv_bfloat16 z = __float2bfloat16(0.f);
    if (tid < L_*R_) { rh[H_+tid] = z; rl[H_+tid] = z; }
    __syncthreads();

    int lane = tid & 31, w = tid >> 5;
    const float4* a4 = (const float4*)(gu_a + (((size_t)l*E_ + e)*R_ + w) * H_);
    const float4* b4 = a4 + (size_t)8 * (H_/4);
    float sa = 0.f, sb = 0.f;
    for (int it = lane; it < H_/4; it += 32) {
        float4 xv = x4[it], av = a4[it], bv = b4[it];
        sa += xv.x*av.x + xv.y*av.y + xv.z*av.z + xv.w*av.w;
        sb += xv.x*bv.x + xv.y*bv.y + xv.z*bv.z + xv.w*bv.w;
    }
    #pragma unroll
    for (int o = 16; o; o >>= 1) {
        sa += __shfl_down_sync(0xffffffffu, sa, o);
        sb += __shfl_down_sync(0xffffffffu, sb, o);
    }
    if (lane == 0) {
        __nv_bfloat16 h, lo2;
        split2(sa, h, lo2); rh[H_+l*R_+w]   = h; rl[H_+l*R_+w]   = lo2;
        split2(sb, h, lo2); rh[H_+l*R_+w+8] = h; rl[H_+l*R_+w+8] = lo2;
    }
}

// ============================================================
// weight conversion
// ============================================================
__global__ __launch_bounds__(256) void k_convw1(
    const float* __restrict__ w13, const float* __restrict__ gu_b) {
    int rc = blockIdx.x, tid = threadIdx.x;
    int e = rc >> 11, c = rc & 2047;
    const float4* src = (const float4*)(w13 + (size_t)rc * H_);
    __nv_bfloat16* bh = g_B1h + (size_t)rc * KT1;
    __nv_bfloat16* bl = g_B1l + (size_t)rc * KT1;
    float4 v0 = src[tid*2], v1 = src[tid*2+1];
    float vv[8] = {v0.x,v0.y,v0.z,v0.w,v1.x,v1.y,v1.z,v1.w};
    __nv_bfloat16 hh[8], ll[8];
    #pragma unroll
    for (int j = 0; j < 8; j++) split2(vv[j], hh[j], ll[j]);
    *(uint4*)(bh + tid*8) = make_uint4(pk2(hh[0],hh[1]),pk2(hh[2],hh[3]),pk2(hh[4],hh[5]),pk2(hh[6],hh[7]));
    *(uint4*)(bl + tid*8) = make_uint4(pk2(ll[0],ll[1]),pk2(ll[2],ll[3]),pk2(ll[4],ll[5]),pk2(ll[6],ll[7]));
    if (tid < L_*R_) {
        int l = tid >> 4, r = tid & 15;
        float v = gu_b[(((size_t)l*E_ + e)*I2_ + c)*R_ + r];
        __nv_bfloat16 h, lo2; split2(v, h, lo2);
        bh[H_+tid] = h; bl[H_+tid] = lo2;
    }
}

__global__ __launch_bounds__(256) void k_convw2(
    const float* __restrict__ w2, const float* __restrict__ d_b) {
    int rc = blockIdx.x, tid = threadIdx.x;
    int e = rc >> 11, c = rc & 2047;
    const float4* src = (const float4*)(w2 + (size_t)rc * I_);
    __nv_bfloat16* bh = g_B2h + (size_t)rc * KT2;
    __nv_bfloat16* bl = g_B2l + (size_t)rc * KT2;
    float4 v0 = src[tid];
    float vv[4] = {v0.x,v0.y,v0.z,v0.w};
    __nv_bfloat16 hh[4], ll[4];
    #pragma unroll
    for (int j = 0; j < 4; j++) split2(vv[j], hh[j], ll[j]);
    *(uint2*)(bh + tid*4) = make_uint2(pk2(hh[0],hh[1]),pk2(hh[2],hh[3]));
    *(uint2*)(bl + tid*4) = make_uint2(pk2(ll[0],ll[1]),pk2(ll[2],ll[3]));
    if (tid < L_*R_) {
        int l = tid >> 4, r = tid & 15;
        float v = d_b[(((size_t)l*E_ + e)*H_ + c)*R_ + r];
        __nv_bfloat16 h, lo2; split2(v, h, lo2);
        bh[I_+tid] = h; bl[I_+tid] = lo2;
    }
}

// ============================================================
// prep2
// ============================================================
__global__ __launch_bounds__(256) void k_prep2(
    const float* __restrict__ d_a,
    const int* __restrict__ topk_ids, const int* __restrict__ lora_idx) {
    int s = blockIdx.x, tid = threadIdx.x;
    int p = g_list[s], t = p >> 1;
    int e = topk_ids[p], l = lora_idx[t];
    __nv_bfloat16* rh = g_A2h + (size_t)s * KT2;
    __nv_bfloat16* rl = g_A2l + (size_t)s * KT2;
    __nv_bfloat16 z = __float2bfloat16(0.f);
    if (tid < L_*R_) { rh[I_+tid] = z; rl[I_+tid] = z; }
    __syncthreads();

    int lane = tid & 31, w = tid >> 5;
    const float2* a2 = (const float2*)(d_a + (((size_t)l*E_ + e)*R_ + w) * I_);
    const float2* b2 = a2 + (size_t)8 * (I_/2);
    const __nv_bfloat162* h2 = (const __nv_bfloat162*)rh;
    const __nv_bfloat162* l2 = (const __nv_bfloat162*)rl;
    float sa = 0.f, sb = 0.f;
    for (int it = lane; it < I_/2; it += 32) {
        float2 fh = __bfloat1622float2(h2[it]);
        float2 fl = __bfloat1622float2(l2[it]);
        float a0 = fh.x + fl.x, a1 = fh.y + fl.y;
        float2 av = a2[it], bv = b2[it];
        sa += a0*av.x + a1*av.y;
        sb += a0*bv.x + a1*bv.y;
    }
    #pragma unroll
    for (int o = 16; o; o >>= 1) {
        sa += __shfl_down_sync(0xffffffffu, sa, o);
        sb += __shfl_down_sync(0xffffffffu, sb, o);
    }
    if (lane == 0) {
        __nv_bfloat16 h, lo2;
        split2(sa, h, lo2); rh[I_+l*R_+w]   = h; rl[I_+l*R_+w]   = lo2;
        split2(sb, h, lo2); rh[I_+l*R_+w+8] = h; rl[I_+l*R_+w+8] = lo2;
    }
}

// ============================================================
// mma.sync GEMM: CTA 128x256, 256 threads / 8 warps (64x64 each).
// K chunk 32 per stage, 3 stages x 48KB. bf16 3-product split in
// three independent passes (hh, hl, lh) to break acc chains.
// ============================================================
#define STAGE 49152
#define SMEMB (3*STAGE)   // 147456

template<int GEMM>
__global__ __launch_bounds__(256, 1) void k_gemm_mma() {
    constexpr int KTOT = (GEMM == 1) ? KT1 : KT2;
    constexpr int NK   = KTOT / 32;
    const __nv_bfloat16* Ah = (GEMM == 1) ? g_A1h : g_A2h;
    const __nv_bfloat16* Al = (GEMM == 1) ? g_A1l : g_A2l;
    const __nv_bfloat16* Bh = (GEMM == 1) ? g_B1h : g_B2h;
    const __nv_bfloat16* Bl = (GEMM == 1) ? g_B1l : g_B2l;

    int e   = blockIdx.z;
    int off = g_off[e];
    int cnt = g_off[e+1] - off;
    int m0  = blockIdx.y * 128;
    if (m0 >= cnt) return;

    extern __shared__ char smem_raw[];
    uint32_t sbase = smem_u32(smem_raw);

    int tid = threadIdx.x;
    int lane = tid & 31, wid = tid >> 5;
    int wm = wid >> 2, wn = wid & 3;   // 2x4 warp grid, 64x64 each

    // ---- loaders ----
    // A: 128 rows x 4 chunks, 2 ids/thread; B: 256 rows x 4 chunks, 4 ids/thread
    size_t aoff[2]; uint32_t sA[2];
    #pragma unroll
    for (int j = 0; j < 2; j++) {
        int id = tid + 256*j, r = id >> 2, c = id & 3;
        int rA = m0 + r; if (rA > cnt-1) rA = cnt-1;
        aoff[j] = (size_t)(off + rA) * KTOT + c*8;
        sA[j]   = swz32(r, c);
    }
    size_t boff[4]; uint32_t sB[4];
    #pragma unroll
    for (int j = 0; j < 4; j++) {
        int id = tid + 256*j, n = id >> 2, c = id & 3;
        int colB;
        if (GEMM == 1) colB = (n < 128) ? (blockIdx.x*128 + n) : (I_ + blockIdx.x*128 + n - 128);
        else           colB = blockIdx.x*256 + n;
        boff[j] = ((size_t)e * 2048 + colB) * KTOT + c*8;
        sB[j]   = swz32(n, c);
    }

    auto issue = [&](int kt) {
        uint32_t st = sbase + (kt % 3) * STAGE;
        size_t kadd = (size_t)kt * 32;
        #pragma unroll
        for (int j = 0; j < 2; j++) {
            cp16(st +        sA[j], Ah + aoff[j] + kadd);
            cp16(st + 8192 + sA[j], Al + aoff[j] + kadd);
        }
        #pragma unroll
        for (int j = 0; j < 4; j++) {
            cp16(st + 16384 + sB[j], Bh + boff[j] + kadd);
            cp16(st + 32768 + sB[j], Bl + boff[j] + kadd);
        }
    };

    // ---- ldmatrix lane geometry ----
    int aRow[4], bRow[4];
    #pragma unroll
    for (int i = 0; i < 4; i++) aRow[i] = wm*64 + i*16 + (lane & 15);
    int aC = (lane >> 4) & 1;
    #pragma unroll
    for (int g = 0; g < 4; g++) bRow[g] = wn*64 + g*16 + (lane & 7) + ((lane & 16) ? 8 : 0);
    int bC = (lane >> 3) & 1;

    float acc[4][8][4];
    #pragma unroll
    for (int i = 0; i < 4; i++)
        #pragma unroll
        for (int j = 0; j < 8; j++)
            #pragma unroll
            for (int q = 0; q < 4; q++) acc[i][j][q] = 0.f;

    issue(0); CP_COMMIT();
    issue(1); CP_COMMIT();

    for (int kt = 0; kt < NK; kt++) {
        CP_WAIT1();
        __syncthreads();
        if (kt + 2 < NK) issue(kt + 2);
        CP_COMMIT();

        uint32_t st = sbase + (kt % 3) * STAGE;
        #pragma unroll
        for (int h = 0; h < 2; h++) {
            uint32_t ah[4][4], al[4][4], bh[4][4], bl[4][4];
            #pragma unroll
            for (int i = 0; i < 4; i++) {
                uint32_t o = swz32(aRow[i], 2*h + aC);
                ldsm4(ah[i], st + o);
                ldsm4(al[i], st + 8192 + o);
            }
            #pragma unroll
            for (int g = 0; g < 4; g++) {
                uint32_t o = swz32(bRow[g], 2*h + bC);
                ldsm4(bh[g], st + 16384 + o);
                ldsm4(bl[g], st + 32768 + o);
            }
            // three independent passes: hh, hl, lh
            #pragma unroll
            for (int i = 0; i < 4; i++)
                #pragma unroll
                for (int j = 0; j < 8; j++)
                    mma_bf16(acc[i][j], ah[i], &bh[j>>1][(j&1)*2]);
            #pragma unroll
            for (int i = 0; i < 4; i++)
                #pragma unroll
                for (int j = 0; j < 8; j++)
                    mma_bf16(acc[i][j], ah[i], &bl[j>>1][(j&1)*2]);
            #pragma unroll
            for (int i = 0; i < 4; i++)
                #pragma unroll
                for (int j = 0; j < 8; j++)
                    mma_bf16(acc[i][j], al[i], &bh[j>>1][(j&1)*2]);
        }
    }
    CP_WAIT0();
    __syncthreads();

    if constexpr (GEMM == 1) {
        float* ex = reinterpret_cast<float*>(smem_raw);   // [128][260] fp32
        #pragma unroll
        for (int i = 0; i < 4; i++)
            #pragma unroll
            for (int j = 0; j < 8; j++) {
                int r0 = wm*64 + i*16 + (lane >> 2);
                int c  = wn*64 + j*8 + (lane & 3)*2;
                ex[r0*260 + c]       = acc[i][j][0];
                ex[r0*260 + c + 1]   = acc[i][j][1];
                ex[(r0+8)*260 + c]   = acc[i][j][2];
                ex[(r0+8)*260 + c+1] = acc[i][j][3];
            }
        __syncthreads();
        int m = tid >> 1, half = tid & 1;   // 64 act cols per thread
        if (m0 + m < cnt) {
            size_t srow = (size_t)(off + m0 + m);
            __nv_bfloat16* dh = g_A2h + srow * KT2 + blockIdx.x*128 + half*64;
            __nv_bfloat16* dl = g_A2l + srow * KT2 + blockIdx.x*128 + half*64;
            const float* gr = ex + m*260 + half*64;
            #pragma unroll
            for (int q = 0; q < 8; q++) {
                uint32_t hw[4], lw[4];
                #pragma unroll
                for (int u = 0; u < 4; u++) {
                    float g0 = gr[q*8 + u*2], g1 = gr[q*8 + u*2 + 1];
                    float u0 = gr[128 + q*8 + u*2], u1 = gr[128 + q*8 + u*2 + 1];
                    float a0 = u0 * g0 / (1.f + expf(-g0));
                    float a1 = u1 * g1 / (1.f + expf(-g1));
                    __nv_bfloat16 h0, l0, h1, l1;
                    split2(a0, h0, l0); split2(a1, h1, l1);
                    hw[u] = pk2(h0, h1); lw[u] = pk2(l0, l1);
                }
                *(uint4*)(dh + q*8) = make_uint4(hw[0], hw[1], hw[2], hw[3]);
                *(uint4*)(dl + q*8) = make_uint4(lw[0], lw[1], lw[2], lw[3]);
            }
        }
    } else {
        int c0 = blockIdx.x * 256;
        #pragma unroll
        for (int i = 0; i < 4; i++) {
            int r0 = m0 + wm*64 + i*16 + (lane >> 2);
            #pragma unroll
            for (int j = 0; j < 8; j++) {
                int c = c0 + wn*64 + j*8 + (lane & 3)*2;
                if (r0 < cnt)
                    *(float2*)(g_D + (size_t)(off + r0) * H_ + c) =
                        make_float2(acc[i][j][0], acc[i][j][1]);
                if (r0 + 8 < cnt)
                    *(float2*)(g_D + (size_t)(off + r0 + 8) * H_ + c) =
                        make_float2(acc[i][j][2], acc[i][j][3]);
            }
        }
    }
}

// ============================================================
// combine
// ============================================================
__global__ __launch_bounds__(256) void k_combine(
    const float* __restrict__ tw, float* __restrict__ out) {
    int idx = blockIdx.x * 256 + threadIdx.x;
    int t = idx >> 9, h4 = idx & 511;
    float w0 = tw[2*t], w1 = tw[2*t+1];
    const float4* d0 = (const float4*)(g_D + (size_t)g_pos[2*t]   * H_);
    const float4* d1 = (const float4*)(g_D + (size_t)g_pos[2*t+1] * H_);
    float4 a = d0[h4], b = d1[h4], o;
    o.x = w0*a.x + w1*b.x; o.y = w0*a.y + w1*b.y;
    o.z = w0*a.z + w1*b.z; o.w = w0*a.w + w1*b.w;
    ((float4*)out)[idx] = o;
}

// ============================================================
extern "C" void kernel_launch(void* const* d_in, const int* in_sizes, int n_in,
                              void* d_out, int out_size) {
    const float* x    = (const float*)d_in[0];
    const float* tw   = (const float*)d_in[1];
    const float* w13  = (const float*)d_in[2];
    const float* w2   = (const float*)d_in[3];
    const float* gu_a = (const float*)d_in[4];
    const float* gu_b = (const float*)d_in[5];
    const float* da   = (const float*)d_in[6];
    const float* db   = (const float*)d_in[7];
    const int*   ids  = (const int*)d_in[8];
    const int*   lidx = (const int*)d_in[9];
    float* out = (float*)d_out;

    cudaFuncSetAttribute(k_gemm_mma<1>, cudaFuncAttributeMaxDynamicSharedMemorySize, SMEMB);
    cudaFuncSetAttribute(k_gemm_mma<2>, cudaFuncAttributeMaxDynamicSharedMemorySize, SMEMB);

    // order chosen so k_gemm_mma<1> is launch #4 (ncu captures it)
    k_route  <<<1, 256>>>(ids, lidx);
    k_convw1 <<<E_*I2_, 256>>>(w13, gu_b);
    k_prep1  <<<P_, 256>>>(x, gu_a, ids, lidx);
    k_gemm_mma<1><<<dim3(8, 64, E_), 256, SMEMB>>>();
    k_convw2 <<<E_*H_,  256>>>(w2, db);
    k_prep2  <<<P_, 256>>>(da, ids, lidx);
    k_gemm_mma<2><<<dim3(8, 64, E_), 256, SMEMB>>>();
    k_combine<<<(T_*H_/4)/256, 256>>>(tw, out);
}

// round 9
// speedup vs baseline: 1.3641x; 1.2708x over previous
#include <cuda_runtime.h>
#include <cuda_fp16.h>
#include <math.h>
#include <stdint.h>

#define E_  8
#define H_  2048
#define I_  1024
#define I2_ 2048
#define L_  4
#define R_  16
#define T_  4096
#define P_  8192

#define KT1 2112     // H + L*R
#define KT2 1088     // I + L*R

// -------- scratch (device globals; allocation-free) --------
__device__ __half g_A1[(size_t)P_*KT1];
__device__ __half g_B1h[(size_t)E_*I2_*KT1], g_B1l[(size_t)E_*I2_*KT1];
__device__ __half g_A2[(size_t)P_*KT2];
__device__ __half g_B2h[(size_t)E_*H_*KT2], g_B2l[(size_t)E_*H_*KT2];
__device__ float g_D[(size_t)P_*H_];
__device__ int   g_list[P_], g_pos[P_], g_off[E_+1];

// -------- helpers --------
__device__ __forceinline__ uint32_t smem_u32(const void* p) {
    uint32_t a;
    asm("{ .reg .u64 t; cvta.to.shared.u64 t, %1; cvt.u32.u64 %0, t; }" : "=r"(a) : "l"(p));
    return a;
}
__device__ __forceinline__ uint32_t pk2(__half a, __half b) {
    __half2 t = __halves2half2(a, b);
    return *reinterpret_cast<uint32_t*>(&t);
}
__device__ __forceinline__ void splitH(float v, __half& h, __half& l) {
    h = __float2half(v);
    l = __float2half(v - __half2float(h));
}
__device__ __forceinline__ void cp16(uint32_t dst, const void* src) {
    asm volatile("cp.async.cg.shared.global [%0], [%1], 16;" :: "r"(dst), "l"(src));
}
#define CP_COMMIT() asm volatile("cp.async.commit_group;" ::: "memory")
#define CP_WAIT1()  asm volatile("cp.async.wait_group 1;" ::: "memory")
#define CP_WAIT0()  asm volatile("cp.async.wait_group 0;" ::: "memory")

__device__ __forceinline__ void ldsm4(uint32_t* r, uint32_t addr) {
    asm volatile("ldmatrix.sync.aligned.m8n8.x4.shared.b16 {%0,%1,%2,%3}, [%4];"
        : "=r"(r[0]), "=r"(r[1]), "=r"(r[2]), "=r"(r[3]) : "r"(addr));
}
__device__ __forceinline__ void mma_f16(float* d, const uint32_t* a, const uint32_t* b) {
    asm volatile(
        "mma.sync.aligned.m16n8k16.row.col.f32.f16.f16.f32 "
        "{%0,%1,%2,%3}, {%4,%5,%6,%7}, {%8,%9}, {%0,%1,%2,%3};"
        : "+f"(d[0]), "+f"(d[1]), "+f"(d[2]), "+f"(d[3])
        : "r"(a[0]), "r"(a[1]), "r"(a[2]), "r"(a[3]), "r"(b[0]), "r"(b[1]));
}
// [rows x 32 fp16] tile, row stride 64B, 4x 16B chunks/row
__device__ __forceinline__ uint32_t swz32(int r, int c) {
    return (uint32_t)(r * 64 + ((c ^ ((r >> 1) & 3)) << 4));
}

// ============================================================
// routing: sort pairs by (expert, lora)
// ============================================================
__global__ void k_route(const int* __restrict__ topk_ids,
                        const int* __restrict__ lora_idx) {
    __shared__ int cnt[E_*L_], cur[E_*L_];
    int tid = threadIdx.x;
    if (tid < E_*L_) cnt[tid] = 0;
    __syncthreads();
    for (int p = tid; p < P_; p += blockDim.x)
        atomicAdd(&cnt[topk_ids[p]*L_ + lora_idx[p>>1]], 1);
    __syncthreads();
    if (tid == 0) {
        int acc = 0;
        for (int b = 0; b < E_*L_; b++) {
            if ((b & (L_-1)) == 0) g_off[b/L_] = acc;
            cur[b] = acc; acc += cnt[b];
        }
        g_off[E_] = acc;
    }
    __syncthreads();
    for (int p = tid; p < P_; p += blockDim.x) {
        int key = topk_ids[p]*L_ + lora_idx[p>>1];
        int pos = atomicAdd(&cur[key], 1);
        g_list[pos] = p;
        g_pos[p]    = pos;
    }
}

// ============================================================
// prep1: A1 row (fp16): [ f16(x[t]) | masked f16(U) ]
// ============================================================
__global__ __launch_bounds__(256) void k_prep1(
    const float* __restrict__ x, const float* __restrict__ gu_a,
    const int* __restrict__ topk_ids, const int* __restrict__ lora_idx) {
    int s = blockIdx.x, tid = threadIdx.x;
    int p = g_list[s], t = p >> 1;
    int e = topk_ids[p], l = lora_idx[t];
    const float4* x4 = (const float4*)(x + (size_t)t * H_);
    __half* ra = g_A1 + (size_t)s * KT1;

    {
        float4 v0 = x4[tid*2], v1 = x4[tid*2+1];
        uint4 u;
        u.x = pk2(__float2half(v0.x), __float2half(v0.y));
        u.y = pk2(__float2half(v0.z), __float2half(v0.w));
        u.z = pk2(__float2half(v1.x), __float2half(v1.y));
        u.w = pk2(__float2half(v1.z), __float2half(v1.w));
        *(uint4*)(ra + tid*8) = u;
    }
    if (tid < L_*R_) ra[H_+tid] = __float2half(0.f);
    __syncthreads();

    int lane = tid & 31, w = tid >> 5;
    const float4* a4 = (const float4*)(gu_a + (((size_t)l*E_ + e)*R_ + w) * H_);
    const float4* b4 = a4 + (size_t)8 * (H_/4);
    float sa = 0.f, sb = 0.f;
    for (int it = lane; it < H_/4; it += 32) {
        float4 xv = x4[it], av = a4[it], bv = b4[it];
        sa += xv.x*av.x + xv.y*av.y + xv.z*av.z + xv.w*av.w;
        sb += xv.x*bv.x + xv.y*bv.y + xv.z*bv.z + xv.w*bv.w;
    }
    #pragma unroll
    for (int o = 16; o; o >>= 1) {
        sa += __shfl_down_sync(0xffffffffu, sa, o);
        sb += __shfl_down_sync(0xffffffffu, sb, o);
    }
    if (lane == 0) {
        ra[H_+l*R_+w]   = __float2half(sa);
        ra[H_+l*R_+w+8] = __float2half(sb);
    }
}

// ============================================================
// weight conversion (fp16 hi/lo)
// ============================================================
__global__ __launch_bounds__(256) void k_convw1(
    const float* __restrict__ w13, const float* __restrict__ gu_b) {
    int rc = blockIdx.x, tid = threadIdx.x;
    int e = rc >> 11, c = rc & 2047;
    const float4* src = (const float4*)(w13 + (size_t)rc * H_);
    __half* bh = g_B1h + (size_t)rc * KT1;
    __half* bl = g_B1l + (size_t)rc * KT1;
    float4 v0 = src[tid*2], v1 = src[tid*2+1];
    float vv[8] = {v0.x,v0.y,v0.z,v0.w,v1.x,v1.y,v1.z,v1.w};
    __half hh[8], ll[8];
    #pragma unroll
    for (int j = 0; j < 8; j++) splitH(vv[j], hh[j], ll[j]);
    *(uint4*)(bh + tid*8) = make_uint4(pk2(hh[0],hh[1]),pk2(hh[2],hh[3]),pk2(hh[4],hh[5]),pk2(hh[6],hh[7]));
    *(uint4*)(bl + tid*8) = make_uint4(pk2(ll[0],ll[1]),pk2(ll[2],ll[3]),pk2(ll[4],ll[5]),pk2(ll[6],ll[7]));
    if (tid < L_*R_) {
        int l = tid >> 4, r = tid & 15;
        float v = gu_b[(((size_t)l*E_ + e)*I2_ + c)*R_ + r];
        __half h, lo2; splitH(v, h, lo2);
        bh[H_+tid] = h; bl[H_+tid] = lo2;
    }
}

__global__ __launch_bounds__(256) void k_convw2(
    const float* __restrict__ w2, const float* __restrict__ d_b) {
    int rc = blockIdx.x, tid = threadIdx.x;
    int e = rc >> 11, c = rc & 2047;
    const float4* src = (const float4*)(w2 + (size_t)rc * I_);
    __half* bh = g_B2h + (size_t)rc * KT2;
    __half* bl = g_B2l + (size_t)rc * KT2;
    float4 v0 = src[tid];
    float vv[4] = {v0.x,v0.y,v0.z,v0.w};
    __half hh[4], ll[4];
    #pragma unroll
    for (int j = 0; j < 4; j++) splitH(vv[j], hh[j], ll[j]);
    *(uint2*)(bh + tid*4) = make_uint2(pk2(hh[0],hh[1]),pk2(hh[2],hh[3]));
    *(uint2*)(bl + tid*4) = make_uint2(pk2(ll[0],ll[1]),pk2(ll[2],ll[3]));
    if (tid < L_*R_) {
        int l = tid >> 4, r = tid & 15;
        float v = d_b[(((size_t)l*E_ + e)*H_ + c)*R_ + r];
        __half h, lo2; splitH(v, h, lo2);
        bh[I_+tid] = h; bl[I_+tid] = lo2;
    }
}

// ============================================================
// prep2: V = act . d_a -> A2 ext (fp16)
// ============================================================
__global__ __launch_bounds__(256) void k_prep2(
    const float* __restrict__ d_a,
    const int* __restrict__ topk_ids, const int* __restrict__ lora_idx) {
    int s = blockIdx.x, tid = threadIdx.x;
    int p = g_list[s], t = p >> 1;
    int e = topk_ids[p], l = lora_idx[t];
    __half* ra = g_A2 + (size_t)s * KT2;
    if (tid < L_*R_) ra[I_+tid] = __float2half(0.f);
    __syncthreads();

    int lane = tid & 31, w = tid >> 5;
    const float2* a2 = (const float2*)(d_a + (((size_t)l*E_ + e)*R_ + w) * I_);
    const float2* b2 = a2 + (size_t)8 * (I_/2);
    const __half2* h2 = (const __half2*)ra;
    float sa = 0.f, sb = 0.f;
    for (int it = lane; it < I_/2; it += 32) {
        float2 fa = __half22float2(h2[it]);
        float2 av = a2[it], bv = b2[it];
        sa += fa.x*av.x + fa.y*av.y;
        sb += fa.x*bv.x + fa.y*bv.y;
    }
    #pragma unroll
    for (int o = 16; o; o >>= 1) {
        sa += __shfl_down_sync(0xffffffffu, sa, o);
        sb += __shfl_down_sync(0xffffffffu, sb, o);
    }
    if (lane == 0) {
        ra[I_+l*R_+w]   = __float2half(sa);
        ra[I_+l*R_+w+8] = __float2half(sb);
    }
}

// ============================================================
// mma.sync GEMM: CTA 128x256, 256 threads / 8 warps (64x64 each).
// fp16 2-product: a_f16*(b_hi) + a_f16*(b_lo). K chunk 32, 3 stages.
// Stage: A 8KB @0, Bh 16KB @8192, Bl 16KB @24576 -> 40KB.
// SMEMB covers max(3 stages = 120KB, GEMM1 epilogue exchange
// 128*260*4 = 133120B).
// ============================================================
#define STAGE 40960
#define SMEMB 135168

template<int GEMM>
__global__ __launch_bounds__(256, 1) void k_gemm_mma() {
    constexpr int KTOT = (GEMM == 1) ? KT1 : KT2;
    constexpr int NK   = KTOT / 32;
    const __half* Aa = (GEMM == 1) ? g_A1 : g_A2;
    const __half* Bh = (GEMM == 1) ? g_B1h : g_B2h;
    const __half* Bl = (GEMM == 1) ? g_B1l : g_B2l;

    int e   = blockIdx.z;
    int off = g_off[e];
    int cnt = g_off[e+1] - off;
    int m0  = blockIdx.y * 128;
    if (m0 >= cnt) return;

    extern __shared__ char smem_raw[];
    uint32_t sbase = smem_u32(smem_raw);

    int tid = threadIdx.x;
    int lane = tid & 31, wid = tid >> 5;
    int wm = wid >> 2, wn = wid & 3;   // 2x4 warp grid, 64x64 each

    // ---- loaders ----
    size_t aoff[2]; uint32_t sA[2];
    #pragma unroll
    for (int j = 0; j < 2; j++) {
        int id = tid + 256*j, r = id >> 2, c = id & 3;
        int rA = m0 + r; if (rA > cnt-1) rA = cnt-1;
        aoff[j] = (size_t)(off + rA) * KTOT + c*8;
        sA[j]   = swz32(r, c);
    }
    size_t boff[4]; uint32_t sB[4];
    #pragma unroll
    for (int j = 0; j < 4; j++) {
        int id = tid + 256*j, n = id >> 2, c = id & 3;
        int colB;
        if (GEMM == 1) colB = (n < 128) ? (blockIdx.x*128 + n) : (I_ + blockIdx.x*128 + n - 128);
        else           colB = blockIdx.x*256 + n;
        boff[j] = ((size_t)e * 2048 + colB) * KTOT + c*8;
        sB[j]   = swz32(n, c);
    }

    auto issue = [&](int kt) {
        uint32_t st = sbase + (kt % 3) * STAGE;
        size_t kadd = (size_t)kt * 32;
        #pragma unroll
        for (int j = 0; j < 2; j++)
            cp16(st + sA[j], Aa + aoff[j] + kadd);
        #pragma unroll
        for (int j = 0; j < 4; j++) {
            cp16(st +  8192 + sB[j], Bh + boff[j] + kadd);
            cp16(st + 24576 + sB[j], Bl + boff[j] + kadd);
        }
    };

    // ---- ldmatrix lane geometry ----
    int aRow[4], bRow[4];
    #pragma unroll
    for (int i = 0; i < 4; i++) aRow[i] = wm*64 + i*16 + (lane & 15);
    int aC = (lane >> 4) & 1;
    #pragma unroll
    for (int g = 0; g < 4; g++) bRow[g] = wn*64 + g*16 + (lane & 7) + ((lane & 16) ? 8 : 0);
    int bC = (lane >> 3) & 1;

    float acc[4][8][4];
    #pragma unroll
    for (int i = 0; i < 4; i++)
        #pragma unroll
        for (int j = 0; j < 8; j++)
            #pragma unroll
            for (int q = 0; q < 4; q++) acc[i][j][q] = 0.f;

    issue(0); CP_COMMIT();
    issue(1); CP_COMMIT();

    for (int kt = 0; kt < NK; kt++) {
        CP_WAIT1();
        __syncthreads();
        if (kt + 2 < NK) issue(kt + 2);
        CP_COMMIT();

        uint32_t st = sbase + (kt % 3) * STAGE;
        #pragma unroll
        for (int h = 0; h < 2; h++) {
            uint32_t ar[4][4], bh[4][4], bl[4][4];
            #pragma unroll
            for (int i = 0; i < 4; i++) {
                uint32_t o = swz32(aRow[i], 2*h + aC);
                ldsm4(ar[i], st + o);
            }
            #pragma unroll
            for (int g = 0; g < 4; g++) {
                uint32_t o = swz32(bRow[g], 2*h + bC);
                ldsm4(bh[g], st +  8192 + o);
                ldsm4(bl[g], st + 24576 + o);
            }
            // two independent passes: a*bh, a*bl
            #pragma unroll
            for (int i = 0; i < 4; i++)
                #pragma unroll
                for (int j = 0; j < 8; j++)
                    mma_f16(acc[i][j], ar[i], &bh[j>>1][(j&1)*2]);
            #pragma unroll
            for (int i = 0; i < 4; i++)
                #pragma unroll
                for (int j = 0; j < 8; j++)
                    mma_f16(acc[i][j], ar[i], &bl[j>>1][(j&1)*2]);
        }
    }
    CP_WAIT0();
    __syncthreads();

    if constexpr (GEMM == 1) {
        float* ex = reinterpret_cast<float*>(smem_raw);   // [128][260] fp32 = 133120B
        #pragma unroll
        for (int i = 0; i < 4; i++)
            #pragma unroll
            for (int j = 0; j < 8; j++) {
                int r0 = wm*64 + i*16 + (lane >> 2);
                int c  = wn*64 + j*8 + (lane & 3)*2;
                ex[r0*260 + c]       = acc[i][j][0];
                ex[r0*260 + c + 1]   = acc[i][j][1];
                ex[(r0+8)*260 + c]   = acc[i][j][2];
                ex[(r0+8)*260 + c+1] = acc[i][j][3];
            }
        __syncthreads();
        int m = tid >> 1, half = tid & 1;   // 64 act cols per thread
        if (m0 + m < cnt) {
            size_t srow = (size_t)(off + m0 + m);
            __half* da = g_A2 + srow * KT2 + blockIdx.x*128 + half*64;
            const float* gr = ex + m*260 + half*64;
            #pragma unroll
            for (int q = 0; q < 8; q++) {
                uint32_t hw[4];
                #pragma unroll
                for (int u = 0; u < 4; u++) {
                    float g0 = gr[q*8 + u*2], g1 = gr[q*8 + u*2 + 1];
                    float u0 = gr[128 + q*8 + u*2], u1 = gr[128 + q*8 + u*2 + 1];
                    float a0 = u0 * g0 / (1.f + expf(-g0));
                    float a1 = u1 * g1 / (1.f + expf(-g1));
                    hw[u] = pk2(__float2half(a0), __float2half(a1));
                }
                *(uint4*)(da + q*8) = make_uint4(hw[0], hw[1], hw[2], hw[3]);
            }
        }
    } else {
        int c0 = blockIdx.x * 256;
        #pragma unroll
        for (int i = 0; i < 4; i++) {
            int r0 = m0 + wm*64 + i*16 + (lane >> 2);
            #pragma unroll
            for (int j = 0; j < 8; j++) {
                int c = c0 + wn*64 + j*8 + (lane & 3)*2;
                if (r0 < cnt)
                    *(float2*)(g_D + (size_t)(off + r0) * H_ + c) =
                        make_float2(acc[i][j][0], acc[i][j][1]);
                if (r0 + 8 < cnt)
                    *(float2*)(g_D + (size_t)(off + r0 + 8) * H_ + c) =
                        make_float2(acc[i][j][2], acc[i][j][3]);
            }
        }
    }
}

// ============================================================
// combine
// ============================================================
__global__ __launch_bounds__(256) void k_combine(
    const float* __restrict__ tw, float* __restrict__ out) {
    int idx = blockIdx.x * 256 + threadIdx.x;
    int t = idx >> 9, h4 = idx & 511;
    float w0 = tw[2*t], w1 = tw[2*t+1];
    const float4* d0 = (const float4*)(g_D + (size_t)g_pos[2*t]   * H_);
    const float4* d1 = (const float4*)(g_D + (size_t)g_pos[2*t+1] * H_);
    float4 a = d0[h4], b = d1[h4], o;
    o.x = w0*a.x + w1*b.x; o.y = w0*a.y + w1*b.y;
    o.z = w0*a.z + w1*b.z; o.w = w0*a.w + w1*b.w;
    ((float4*)out)[idx] = o;
}

// ============================================================
extern "C" void kernel_launch(void* const* d_in, const int* in_sizes, int n_in,
                              void* d_out, int out_size) {
    const float* x    = (const float*)d_in[0];
    const float* tw   = (const float*)d_in[1];
    const float* w13  = (const float*)d_in[2];
    const float* w2   = (const float*)d_in[3];
    const float* gu_a = (const float*)d_in[4];
    const float* gu_b = (const float*)d_in[5];
    const float* da   = (const float*)d_in[6];
    const float* db   = (const float*)d_in[7];
    const int*   ids  = (const int*)d_in[8];
    const int*   lidx = (const int*)d_in[9];
    float* out = (float*)d_out;

    cudaFuncSetAttribute(k_gemm_mma<1>, cudaFuncAttributeMaxDynamicSharedMemorySize, SMEMB);
    cudaFuncSetAttribute(k_gemm_mma<2>, cudaFuncAttributeMaxDynamicSharedMemorySize, SMEMB);

    // order chosen so k_gemm_mma<1> is launch #4 (ncu captures it)
    k_route  <<<1, 256>>>(ids, lidx);
    k_convw1 <<<E_*I2_, 256>>>(w13, gu_b);
    k_prep1  <<<P_, 256>>>(x, gu_a, ids, lidx);
    k_gemm_mma<1><<<dim3(8, 64, E_), 256, SMEMB>>>();
    k_convw2 <<<E_*H_,  256>>>(w2, db);
    k_prep2  <<<P_, 256>>>(da, ids, lidx);
    k_gemm_mma<2><<<dim3(8, 64, E_), 256, SMEMB>>>();
    k_combine<<<(T_*H_/4)/256, 256>>>(tw, out);
}

// round 10
// speedup vs baseline: 1.9442x; 1.4252x over previous
#include <cuda_runtime.h>
#include <cuda_fp16.h>
#include <math.h>
#include <stdint.h>

#define E_  8
#define H_  2048
#define I_  1024
#define I2_ 2048
#define L_  4
#define R_  16
#define T_  4096
#define P_  8192

#define KT1 2112     // H + L*R
#define KT2 1088     // I + L*R

// -------- scratch (device globals; allocation-free) --------
__device__ __half g_A1[(size_t)P_*KT1];
__device__ __half g_B1[(size_t)E_*I2_*KT1];
__device__ __half g_A2[(size_t)P_*KT2];
__device__ __half g_B2[(size_t)E_*H_*KT2];
__device__ float g_D[(size_t)P_*H_];
__device__ int   g_list[P_], g_pos[P_], g_off[E_+1];

// -------- helpers --------
__device__ __forceinline__ uint32_t smem_u32(const void* p) {
    uint32_t a;
    asm("{ .reg .u64 t; cvta.to.shared.u64 t, %1; cvt.u32.u64 %0, t; }" : "=r"(a) : "l"(p));
    return a;
}
__device__ __forceinline__ uint32_t pk2(__half a, __half b) {
    __half2 t = __halves2half2(a, b);
    return *reinterpret_cast<uint32_t*>(&t);
}
__device__ __forceinline__ void cp16(uint32_t dst, const void* src) {
    asm volatile("cp.async.cg.shared.global [%0], [%1], 16;" :: "r"(dst), "l"(src));
}
#define CP_COMMIT() asm volatile("cp.async.commit_group;" ::: "memory")
#define CP_WAIT1()  asm volatile("cp.async.wait_group 1;" ::: "memory")
#define CP_WAIT0()  asm volatile("cp.async.wait_group 0;" ::: "memory")

__device__ __forceinline__ void ldsm4(uint32_t* r, uint32_t addr) {
    asm volatile("ldmatrix.sync.aligned.m8n8.x4.shared.b16 {%0,%1,%2,%3}, [%4];"
        : "=r"(r[0]), "=r"(r[1]), "=r"(r[2]), "=r"(r[3]) : "r"(addr));
}
__device__ __forceinline__ void mma_f16(float* d, const uint32_t* a, const uint32_t* b) {
    asm volatile(
        "mma.sync.aligned.m16n8k16.row.col.f32.f16.f16.f32 "
        "{%0,%1,%2,%3}, {%4,%5,%6,%7}, {%8,%9}, {%0,%1,%2,%3};"
        : "+f"(d[0]), "+f"(d[1]), "+f"(d[2]), "+f"(d[3])
        : "r"(a[0]), "r"(a[1]), "r"(a[2]), "r"(a[3]), "r"(b[0]), "r"(b[1]));
}
// [rows x 32 fp16] tile, row stride 64B, 4x 16B chunks/row
__device__ __forceinline__ uint32_t swz32(int r, int c) {
    return (uint32_t)(r * 64 + ((c ^ ((r >> 1) & 3)) << 4));
}

// ============================================================
// routing: sort pairs by (expert, lora)
// ============================================================
__global__ void k_route(const int* __restrict__ topk_ids,
                        const int* __restrict__ lora_idx) {
    __shared__ int cnt[E_*L_], cur[E_*L_];
    int tid = threadIdx.x;
    if (tid < E_*L_) cnt[tid] = 0;
    __syncthreads();
    for (int p = tid; p < P_; p += blockDim.x)
        atomicAdd(&cnt[topk_ids[p]*L_ + lora_idx[p>>1]], 1);
    __syncthreads();
    if (tid == 0) {
        int acc = 0;
        for (int b = 0; b < E_*L_; b++) {
            if ((b & (L_-1)) == 0) g_off[b/L_] = acc;
            cur[b] = acc; acc += cnt[b];
        }
        g_off[E_] = acc;
    }
    __syncthreads();
    for (int p = tid; p < P_; p += blockDim.x) {
        int key = topk_ids[p]*L_ + lora_idx[p>>1];
        int pos = atomicAdd(&cur[key], 1);
        g_list[pos] = p;
        g_pos[p]    = pos;
    }
}

// ============================================================
// prep1: A1 row (fp16): [ f16(x[t]) | masked f16(U) ]
// ============================================================
__global__ __launch_bounds__(256) void k_prep1(
    const float* __restrict__ x, const float* __restrict__ gu_a,
    const int* __restrict__ topk_ids, const int* __restrict__ lora_idx) {
    int s = blockIdx.x, tid = threadIdx.x;
    int p = g_list[s], t = p >> 1;
    int e = topk_ids[p], l = lora_idx[t];
    const float4* x4 = (const float4*)(x + (size_t)t * H_);
    __half* ra = g_A1 + (size_t)s * KT1;

    {
        float4 v0 = x4[tid*2], v1 = x4[tid*2+1];
        uint4 u;
        u.x = pk2(__float2half(v0.x), __float2half(v0.y));
        u.y = pk2(__float2half(v0.z), __float2half(v0.w));
        u.z = pk2(__float2half(v1.x), __float2half(v1.y));
        u.w = pk2(__float2half(v1.z), __float2half(v1.w));
        *(uint4*)(ra + tid*8) = u;
    }
    if (tid < L_*R_) ra[H_+tid] = __float2half(0.f);
    __syncthreads();

    int lane = tid & 31, w = tid >> 5;
    const float4* a4 = (const float4*)(gu_a + (((size_t)l*E_ + e)*R_ + w) * H_);
    const float4* b4 = a4 + (size_t)8 * (H_/4);
    float sa = 0.f, sb = 0.f;
    for (int it = lane; it < H_/4; it += 32) {
        float4 xv = x4[it], av = a4[it], bv = b4[it];
        sa += xv.x*av.x + xv.y*av.y + xv.z*av.z + xv.w*av.w;
        sb += xv.x*bv.x + xv.y*bv.y + xv.z*bv.z + xv.w*bv.w;
    }
    #pragma unroll
    for (int o = 16; o; o >>= 1) {
        sa += __shfl_down_sync(0xffffffffu, sa, o);
        sb += __shfl_down_sync(0xffffffffu, sb, o);
    }
    if (lane == 0) {
        ra[H_+l*R_+w]   = __float2half(sa);
        ra[H_+l*R_+w+8] = __float2half(sb);
    }
}

// ============================================================
// weight conversion (fp16, single)
// ============================================================
__global__ __launch_bounds__(256) void k_convw1(
    const float* __restrict__ w13, const float* __restrict__ gu_b) {
    int rc = blockIdx.x, tid = threadIdx.x;
    int e = rc >> 11, c = rc & 2047;
    const float4* src = (const float4*)(w13 + (size_t)rc * H_);
    __half* bh = g_B1 + (size_t)rc * KT1;
    float4 v0 = src[tid*2], v1 = src[tid*2+1];
    uint4 u;
    u.x = pk2(__float2half(v0.x), __float2half(v0.y));
    u.y = pk2(__float2half(v0.z), __float2half(v0.w));
    u.z = pk2(__float2half(v1.x), __float2half(v1.y));
    u.w = pk2(__float2half(v1.z), __float2half(v1.w));
    *(uint4*)(bh + tid*8) = u;
    if (tid < L_*R_) {
        int l = tid >> 4, r = tid & 15;
        bh[H_+tid] = __float2half(gu_b[(((size_t)l*E_ + e)*I2_ + c)*R_ + r]);
    }
}

__global__ __launch_bounds__(256) void k_convw2(
    const float* __restrict__ w2, const float* __restrict__ d_b) {
    int rc = blockIdx.x, tid = threadIdx.x;
    int e = rc >> 11, c = rc & 2047;
    const float4* src = (const float4*)(w2 + (size_t)rc * I_);
    __half* bh = g_B2 + (size_t)rc * KT2;
    float4 v0 = src[tid];
    *(uint2*)(bh + tid*4) = make_uint2(
        pk2(__float2half(v0.x), __float2half(v0.y)),
        pk2(__float2half(v0.z), __float2half(v0.w)));
    if (tid < L_*R_) {
        int l = tid >> 4, r = tid & 15;
        bh[I_+tid] = __float2half(d_b[(((size_t)l*E_ + e)*H_ + c)*R_ + r]);
    }
}

// ============================================================
// prep2: V = act . d_a -> A2 ext (fp16)
// ============================================================
__global__ __launch_bounds__(256) void k_prep2(
    const float* __restrict__ d_a,
    const int* __restrict__ topk_ids, const int* __restrict__ lora_idx) {
    int s = blockIdx.x, tid = threadIdx.x;
    int p = g_list[s], t = p >> 1;
    int e = topk_ids[p], l = lora_idx[t];
    __half* ra = g_A2 + (size_t)s * KT2;
    if (tid < L_*R_) ra[I_+tid] = __float2half(0.f);
    __syncthreads();

    int lane = tid & 31, w = tid >> 5;
    const float2* a2 = (const float2*)(d_a + (((size_t)l*E_ + e)*R_ + w) * I_);
    const float2* b2 = a2 + (size_t)8 * (I_/2);
    const __half2* h2 = (const __half2*)ra;
    float sa = 0.f, sb = 0.f;
    for (int it = lane; it < I_/2; it += 32) {
        float2 fa = __half22float2(h2[it]);
        float2 av = a2[it], bv = b2[it];
        sa += fa.x*av.x + fa.y*av.y;
        sb += fa.x*bv.x + fa.y*bv.y;
    }
    #pragma unroll
    for (int o = 16; o; o >>= 1) {
        sa += __shfl_down_sync(0xffffffffu, sa, o);
        sb += __shfl_down_sync(0xffffffffu, sb, o);
    }
    if (lane == 0) {
        ra[I_+l*R_+w]   = __float2half(sa);
        ra[I_+l*R_+w+8] = __float2half(sb);
    }
}

// ============================================================
// mma.sync GEMM: CTA 128x256, 256 threads / 8 warps (64x64 each).
// Pure fp16 single product. K chunk 32, 3 stages x 24KB.
// Stage: A 8KB @0, B 16KB @8192.
// SMEMB covers GEMM1 epilogue exchange 128*260*4 = 133120B.
// ============================================================
#define STAGE 24576
#define SMEMB 135168

template<int GEMM>
__global__ __launch_bounds__(256, 1) void k_gemm_mma() {
    constexpr int KTOT = (GEMM == 1) ? KT1 : KT2;
    constexpr int NK   = KTOT / 32;
    const __half* Aa = (GEMM == 1) ? g_A1 : g_A2;
    const __half* Bb = (GEMM == 1) ? g_B1 : g_B2;

    int e   = blockIdx.z;
    int off = g_off[e];
    int cnt = g_off[e+1] - off;
    int m0  = blockIdx.y * 128;
    if (m0 >= cnt) return;

    extern __shared__ char smem_raw[];
    uint32_t sbase = smem_u32(smem_raw);

    int tid = threadIdx.x;
    int lane = tid & 31, wid = tid >> 5;
    int wm = wid >> 2, wn = wid & 3;   // 2x4 warp grid, 64x64 each

    // ---- loaders ----
    size_t aoff[2]; uint32_t sA[2];
    #pragma unroll
    for (int j = 0; j < 2; j++) {
        int id = tid + 256*j, r = id >> 2, c = id & 3;
        int rA = m0 + r; if (rA > cnt-1) rA = cnt-1;
        aoff[j] = (size_t)(off + rA) * KTOT + c*8;
        sA[j]   = swz32(r, c);
    }
    size_t boff[4]; uint32_t sB[4];
    #pragma unroll
    for (int j = 0; j < 4; j++) {
        int id = tid + 256*j, n = id >> 2, c = id & 3;
        int colB;
        if (GEMM == 1) colB = (n < 128) ? (blockIdx.x*128 + n) : (I_ + blockIdx.x*128 + n - 128);
        else           colB = blockIdx.x*256 + n;
        boff[j] = ((size_t)e * 2048 + colB) * KTOT + c*8;
        sB[j]   = swz32(n, c);
    }

    auto issue = [&](int kt) {
        uint32_t st = sbase + (kt % 3) * STAGE;
        size_t kadd = (size_t)kt * 32;
        #pragma unroll
        for (int j = 0; j < 2; j++)
            cp16(st + sA[j], Aa + aoff[j] + kadd);
        #pragma unroll
        for (int j = 0; j < 4; j++)
            cp16(st + 8192 + sB[j], Bb + boff[j] + kadd);
    };

    // ---- ldmatrix lane geometry ----
    int aRow[4], bRow[4];
    #pragma unroll
    for (int i = 0; i < 4; i++) aRow[i] = wm*64 + i*16 + (lane & 15);
    int aC = (lane >> 4) & 1;
    #pragma unroll
    for (int g = 0; g < 4; g++) bRow[g] = wn*64 + g*16 + (lane & 7) + ((lane & 16) ? 8 : 0);
    int bC = (lane >> 3) & 1;

    float acc[4][8][4];
    #pragma unroll
    for (int i = 0; i < 4; i++)
        #pragma unroll
        for (int j = 0; j < 8; j++)
            #pragma unroll
            for (int q = 0; q < 4; q++) acc[i][j][q] = 0.f;

    issue(0); CP_COMMIT();
    issue(1); CP_COMMIT();

    for (int kt = 0; kt < NK; kt++) {
        CP_WAIT1();
        __syncthreads();
        if (kt + 2 < NK) issue(kt + 2);
        CP_COMMIT();

        uint32_t st = sbase + (kt % 3) * STAGE;
        #pragma unroll
        for (int h = 0; h < 2; h++) {
            uint32_t ar[4][4], br[4][4];
            #pragma unroll
            for (int i = 0; i < 4; i++) {
                uint32_t o = swz32(aRow[i], 2*h + aC);
                ldsm4(ar[i], st + o);
            }
            #pragma unroll
            for (int g = 0; g < 4; g++) {
                uint32_t o = swz32(bRow[g], 2*h + bC);
                ldsm4(br[g], st + 8192 + o);
            }
            #pragma unroll
            for (int i = 0; i < 4; i++)
                #pragma unroll
                for (int j = 0; j < 8; j++)
                    mma_f16(acc[i][j], ar[i], &br[j>>1][(j&1)*2]);
        }
    }
    CP_WAIT0();
    __syncthreads();

    if constexpr (GEMM == 1) {
        float* ex = reinterpret_cast<float*>(smem_raw);   // [128][260] fp32 = 133120B
        #pragma unroll
        for (int i = 0; i < 4; i++)
            #pragma unroll
            for (int j = 0; j < 8; j++) {
                int r0 = wm*64 + i*16 + (lane >> 2);
                int c  = wn*64 + j*8 + (lane & 3)*2;
                ex[r0*260 + c]       = acc[i][j][0];
                ex[r0*260 + c + 1]   = acc[i][j][1];
                ex[(r0+8)*260 + c]   = acc[i][j][2];
                ex[(r0+8)*260 + c+1] = acc[i][j][3];
            }
        __syncthreads();
        int m = tid >> 1, half = tid & 1;   // 64 act cols per thread
        if (m0 + m < cnt) {
            size_t srow = (size_t)(off + m0 + m);
            __half* da = g_A2 + srow * KT2 + blockIdx.x*128 + half*64;
            const float* gr = ex + m*260 + half*64;
            #pragma unroll
            for (int q = 0; q < 8; q++) {
                uint32_t hw[4];
                #pragma unroll
                for (int u = 0; u < 4; u++) {
                    float g0 = gr[q*8 + u*2], g1 = gr[q*8 + u*2 + 1];
                    float u0 = gr[128 + q*8 + u*2], u1 = gr[128 + q*8 + u*2 + 1];
                    float a0 = u0 * g0 / (1.f + expf(-g0));
                    float a1 = u1 * g1 / (1.f + expf(-g1));
                    hw[u] = pk2(__float2half(a0), __float2half(a1));
                }
                *(uint4*)(da + q*8) = make_uint4(hw[0], hw[1], hw[2], hw[3]);
            }
        }
    } else {
        int c0 = blockIdx.x * 256;
        #pragma unroll
        for (int i = 0; i < 4; i++) {
            int r0 = m0 + wm*64 + i*16 + (lane >> 2);
            #pragma unroll
            for (int j = 0; j < 8; j++) {
                int c = c0 + wn*64 + j*8 + (lane & 3)*2;
                if (r0 < cnt)
                    *(float2*)(g_D + (size_t)(off + r0) * H_ + c) =
                        make_float2(acc[i][j][0], acc[i][j][1]);
                if (r0 + 8 < cnt)
                    *(float2*)(g_D + (size_t)(off + r0 + 8) * H_ + c) =
                        make_float2(acc[i][j][2], acc[i][j][3]);
            }
        }
    }
}

// ============================================================
// combine
// ============================================================
__global__ __launch_bounds__(256) void k_combine(
    const float* __restrict__ tw, float* __restrict__ out) {
    int idx = blockIdx.x * 256 + threadIdx.x;
    int t = idx >> 9, h4 = idx & 511;
    float w0 = tw[2*t], w1 = tw[2*t+1];
    const float4* d0 = (const float4*)(g_D + (size_t)g_pos[2*t]   * H_);
    const float4* d1 = (const float4*)(g_D + (size_t)g_pos[2*t+1] * H_);
    float4 a = d0[h4], b = d1[h4], o;
    o.x = w0*a.x + w1*b.x; o.y = w0*a.y + w1*b.y;
    o.z = w0*a.z + w1*b.z; o.w = w0*a.w + w1*b.w;
    ((float4*)out)[idx] = o;
}

// ============================================================
extern "C" void kernel_launch(void* const* d_in, const int* in_sizes, int n_in,
                              void* d_out, int out_size) {
    const float* x    = (const float*)d_in[0];
    const float* tw   = (const float*)d_in[1];
    const float* w13  = (const float*)d_in[2];
    const float* w2   = (const float*)d_in[3];
    const float* gu_a = (const float*)d_in[4];
    const float* gu_b = (const float*)d_in[5];
    const float* da   = (const float*)d_in[6];
    const float* db   = (const float*)d_in[7];
    const int*   ids  = (const int*)d_in[8];
    const int*   lidx = (const int*)d_in[9];
    float* out = (float*)d_out;

    cudaFuncSetAttribute(k_gemm_mma<1>, cudaFuncAttributeMaxDynamicSharedMemorySize, SMEMB);
    cudaFuncSetAttribute(k_gemm_mma<2>, cudaFuncAttributeMaxDynamicSharedMemorySize, SMEMB);

    // order chosen so k_gemm_mma<1> is launch #4 (ncu captures it)
    k_route  <<<1, 256>>>(ids, lidx);
    k_convw1 <<<E_*I2_, 256>>>(w13, gu_b);
    k_prep1  <<<P_, 256>>>(x, gu_a, ids, lidx);
    k_gemm_mma<1><<<dim3(8, 64, E_), 256, SMEMB>>>();
    k_convw2 <<<E_*H_,  256>>>(w2, db);
    k_prep2  <<<P_, 256>>>(da, ids, lidx);
    k_gemm_mma<2><<<dim3(8, 64, E_), 256, SMEMB>>>();
    k_combine<<<(T_*H_/4)/256, 256>>>(tw, out);
}

// round 11
// speedup vs baseline: 2.2207x; 1.1423x over previous
#include <cuda_runtime.h>
#include <cuda_fp16.h>
#include <math.h>
#include <stdint.h>

#define E_  8
#define H_  2048
#define I_  1024
#define I2_ 2048
#define L_  4
#define R_  16
#define T_  4096
#define P_  8192

#define KT1 2112     // H + L*R  (33 * 64)
#define KT2 1088     // I + L*R  (17 * 64)

// -------- scratch (device globals; allocation-free) --------
__device__ __half g_Xh[(size_t)T_*H_];          // fp16 x, one row per token
__device__ __half g_U1[(size_t)P_*64];          // per-pair LoRA ext for GEMM1
__device__ __half g_B1[(size_t)E_*I2_*KT1];
__device__ __half g_A2[(size_t)P_*KT2];         // act (cw-scaled) + V ext
__device__ __half g_B2[(size_t)E_*H_*KT2];
__device__ __half g_Dh[(size_t)P_*H_];          // cw-scaled down output, fp16
__device__ int   g_list[P_], g_pos[P_], g_off[E_+1];

// -------- helpers --------
__device__ __forceinline__ uint32_t smem_u32(const void* p) {
    uint32_t a;
    asm("{ .reg .u64 t; cvta.to.shared.u64 t, %1; cvt.u32.u64 %0, t; }" : "=r"(a) : "l"(p));
    return a;
}
__device__ __forceinline__ uint32_t pk2(__half a, __half b) {
    __half2 t = __halves2half2(a, b);
    return *reinterpret_cast<uint32_t*>(&t);
}
__device__ __forceinline__ void cp16(uint32_t dst, const void* src) {
    asm volatile("cp.async.cg.shared.global [%0], [%1], 16;" :: "r"(dst), "l"(src));
}
#define CP_COMMIT() asm volatile("cp.async.commit_group;" ::: "memory")
#define CP_WAIT1()  asm volatile("cp.async.wait_group 1;" ::: "memory")
#define CP_WAIT0()  asm volatile("cp.async.wait_group 0;" ::: "memory")

__device__ __forceinline__ void ldsm4(uint32_t* r, uint32_t addr) {
    asm volatile("ldmatrix.sync.aligned.m8n8.x4.shared.b16 {%0,%1,%2,%3}, [%4];"
        : "=r"(r[0]), "=r"(r[1]), "=r"(r[2]), "=r"(r[3]) : "r"(addr));
}
__device__ __forceinline__ void mma_f16(float* d, const uint32_t* a, const uint32_t* b) {
    asm volatile(
        "mma.sync.aligned.m16n8k16.row.col.f32.f16.f16.f32 "
        "{%0,%1,%2,%3}, {%4,%5,%6,%7}, {%8,%9}, {%0,%1,%2,%3};"
        : "+f"(d[0]), "+f"(d[1]), "+f"(d[2]), "+f"(d[3])
        : "r"(a[0]), "r"(a[1]), "r"(a[2]), "r"(a[3]), "r"(b[0]), "r"(b[1]));
}
// [rows x 64 fp16] tile, row stride 128B, 8x 16B chunks/row
__device__ __forceinline__ uint32_t swz64(int r, int c) {
    return (uint32_t)(r * 128 + ((c ^ (r & 7)) << 4));
}

// ============================================================
// routing: sort pairs by (expert, lora)
// ============================================================
__global__ void k_route(const int* __restrict__ topk_ids,
                        const int* __restrict__ lora_idx) {
    __shared__ int cnt[E_*L_], cur[E_*L_];
    int tid = threadIdx.x;
    if (tid < E_*L_) cnt[tid] = 0;
    __syncthreads();
    for (int p = tid; p < P_; p += blockDim.x)
        atomicAdd(&cnt[topk_ids[p]*L_ + lora_idx[p>>1]], 1);
    __syncthreads();
    if (tid == 0) {
        int acc = 0;
        for (int b = 0; b < E_*L_; b++) {
            if ((b & (L_-1)) == 0) g_off[b/L_] = acc;
            cur[b] = acc; acc += cnt[b];
        }
        g_off[E_] = acc;
    }
    __syncthreads();
    for (int p = tid; p < P_; p += blockDim.x) {
        int key = topk_ids[p]*L_ + lora_idx[p>>1];
        int pos = atomicAdd(&cur[key], 1);
        g_list[pos] = p;
        g_pos[p]    = pos;
    }
}

// ============================================================
// prep1: convert x once per token (pair with even p) + U ext per pair
// ============================================================
__global__ __launch_bounds__(256) void k_prep1(
    const float* __restrict__ x, const float* __restrict__ gu_a,
    const int* __restrict__ topk_ids, const int* __restrict__ lora_idx) {
    int s = blockIdx.x, tid = threadIdx.x;
    int p = g_list[s], t = p >> 1;
    int e = topk_ids[p], l = lora_idx[t];
    const float4* x4 = (const float4*)(x + (size_t)t * H_);

    if ((p & 1) == 0) {     // convert x[t] exactly once
        float4 v0 = x4[tid*2], v1 = x4[tid*2+1];
        uint4 u;
        u.x = pk2(__float2half(v0.x), __float2half(v0.y));
        u.y = pk2(__float2half(v0.z), __float2half(v0.w));
        u.z = pk2(__float2half(v1.x), __float2half(v1.y));
        u.w = pk2(__float2half(v1.z), __float2half(v1.w));
        *(uint4*)(g_Xh + (size_t)t * H_ + tid*8) = u;
    }
    __half* ru = g_U1 + (size_t)s * 64;
    if (tid < 64) ru[tid] = __float2half(0.f);
    __syncthreads();

    int lane = tid & 31, w = tid >> 5;
    const float4* a4 = (const float4*)(gu_a + (((size_t)l*E_ + e)*R_ + w) * H_);
    const float4* b4 = a4 + (size_t)8 * (H_/4);
    float sa = 0.f, sb = 0.f;
    for (int it = lane; it < H_/4; it += 32) {
        float4 xv = x4[it], av = a4[it], bv = b4[it];
        sa += xv.x*av.x + xv.y*av.y + xv.z*av.z + xv.w*av.w;
        sb += xv.x*bv.x + xv.y*bv.y + xv.z*bv.z + xv.w*bv.w;
    }
    #pragma unroll
    for (int o = 16; o; o >>= 1) {
        sa += __shfl_down_sync(0xffffffffu, sa, o);
        sb += __shfl_down_sync(0xffffffffu, sb, o);
    }
    if (lane == 0) {
        ru[l*R_+w]   = __float2half(sa);
        ru[l*R_+w+8] = __float2half(sb);
    }
}

// ============================================================
// weight conversion (fp16)
// ============================================================
__global__ __launch_bounds__(256) void k_convw1(
    const float* __restrict__ w13, const float* __restrict__ gu_b) {
    int rc = blockIdx.x, tid = threadIdx.x;
    int e = rc >> 11, c = rc & 2047;
    const float4* src = (const float4*)(w13 + (size_t)rc * H_);
    __half* bh = g_B1 + (size_t)rc * KT1;
    float4 v0 = src[tid*2], v1 = src[tid*2+1];
    uint4 u;
    u.x = pk2(__float2half(v0.x), __float2half(v0.y));
    u.y = pk2(__float2half(v0.z), __float2half(v0.w));
    u.z = pk2(__float2half(v1.x), __float2half(v1.y));
    u.w = pk2(__float2half(v1.z), __float2half(v1.w));
    *(uint4*)(bh + tid*8) = u;
    if (tid < L_*R_) {
        int l = tid >> 4, r = tid & 15;
        bh[H_+tid] = __float2half(gu_b[(((size_t)l*E_ + e)*I2_ + c)*R_ + r]);
    }
}

__global__ __launch_bounds__(256) void k_convw2(
    const float* __restrict__ w2, const float* __restrict__ d_b) {
    int rc = blockIdx.x, tid = threadIdx.x;
    int e = rc >> 11, c = rc & 2047;
    const float4* src = (const float4*)(w2 + (size_t)rc * I_);
    __half* bh = g_B2 + (size_t)rc * KT2;
    float4 v0 = src[tid];
    *(uint2*)(bh + tid*4) = make_uint2(
        pk2(__float2half(v0.x), __float2half(v0.y)),
        pk2(__float2half(v0.z), __float2half(v0.w)));
    if (tid < L_*R_) {
        int l = tid >> 4, r = tid & 15;
        bh[I_+tid] = __float2half(d_b[(((size_t)l*E_ + e)*H_ + c)*R_ + r]);
    }
}

// ============================================================
// prep2: V = (cw*act) . d_a -> A2 ext (fp16)
// ============================================================
__global__ __launch_bounds__(256) void k_prep2(
    const float* __restrict__ d_a,
    const int* __restrict__ topk_ids, const int* __restrict__ lora_idx) {
    int s = blockIdx.x, tid = threadIdx.x;
    int p = g_list[s], t = p >> 1;
    int e = topk_ids[p], l = lora_idx[t];
    __half* ra = g_A2 + (size_t)s * KT2;
    if (tid < L_*R_) ra[I_+tid] = __float2half(0.f);
    __syncthreads();

    int lane = tid & 31, w = tid >> 5;
    const float2* a2 = (const float2*)(d_a + (((size_t)l*E_ + e)*R_ + w) * I_);
    const float2* b2 = a2 + (size_t)8 * (I_/2);
    const __half2* h2 = (const __half2*)ra;
    float sa = 0.f, sb = 0.f;
    for (int it = lane; it < I_/2; it += 32) {
        float2 fa = __half22float2(h2[it]);
        float2 av = a2[it], bv = b2[it];
        sa += fa.x*av.x + fa.y*av.y;
        sb += fa.x*bv.x + fa.y*bv.y;
    }
    #pragma unroll
    for (int o = 16; o; o >>= 1) {
        sa += __shfl_down_sync(0xffffffffu, sa, o);
        sb += __shfl_down_sync(0xffffffffu, sb, o);
    }
    if (lane == 0) {
        ra[I_+l*R_+w]   = __float2half(sa);
        ra[I_+l*R_+w+8] = __float2half(sb);
    }
}

// ============================================================
// mma.sync GEMM: CTA 128x256, 256 threads / 8 warps (64x64 each).
// Pure fp16, K chunk 64, 3 stages x 48KB (A 16KB @0, B 32KB @16384).
// GEMM1: A = g_Xh[token] (k<2048) ++ g_U1[pair]; epilogue SwiGLU*cw -> A2.
// GEMM2: A = g_A2; epilogue -> g_Dh fp16.
// ============================================================
#define STAGE 49152
#define SMEMB (3*STAGE)   // 147456 >= exchange 133120

template<int GEMM>
__global__ __launch_bounds__(256, 1) void k_gemm_mma(const float* __restrict__ tw) {
    constexpr int KTOT = (GEMM == 1) ? KT1 : KT2;
    constexpr int NK   = KTOT / 64;     // 33 / 17
    constexpr int NKX  = NK - 1;        // last kt is the LoRA-ext chunk (GEMM1)
    const __half* Bb = (GEMM == 1) ? g_B1 : g_B2;

    int e   = blockIdx.z;
    int off = g_off[e];
    int cnt = g_off[e+1] - off;
    int m0  = blockIdx.y * 128;
    if (m0 >= cnt) return;

    extern __shared__ char smem_raw[];
    uint32_t sbase = smem_u32(smem_raw);

    int tid = threadIdx.x;
    int lane = tid & 31, wid = tid >> 5;
    int wm = wid >> 2, wn = wid & 3;   // 2x4 warp grid, 64x64 each

    // ---- loader setup: A 128 rows x 8 chunks (4/thread), B 256 x 8 (8/thread) ----
    uint32_t aX[4], aU[4], sAo[4];
    #pragma unroll
    for (int j = 0; j < 4; j++) {
        int id = tid + 256*j, r = id >> 3, c = id & 7;
        int rA = m0 + r; if (rA > cnt-1) rA = cnt-1;
        int srow = off + rA;
        if (GEMM == 1) {
            int p = g_list[srow];
            aX[j] = (uint32_t)(p >> 1) * H_ + c*8;   // token x row
            aU[j] = (uint32_t)srow * 64 + c*8;       // pair ext row
        } else {
            aX[j] = (uint32_t)srow * KT2 + c*8;
        }
        sAo[j] = swz64(r, c);
    }
    uint32_t bO[8], sBo[8];
    #pragma unroll
    for (int j = 0; j < 8; j++) {
        int id = tid + 256*j, n = id >> 3, c = id & 7;
        int colB;
        if (GEMM == 1) colB = blockIdx.x*128 + (n & 127) + ((n >> 7) * I_);
        else           colB = blockIdx.x*256 + n;
        bO[j] = ((uint32_t)e * 2048 + colB) * KTOT + c*8;
        sBo[j] = swz64(n, c);
    }

    auto issue = [&](int kt) {
        uint32_t st = sbase + (kt % 3) * STAGE;
        uint32_t kadd = (uint32_t)kt * 64;
        #pragma unroll
        for (int j = 0; j < 4; j++) {
            const __half* src;
            if (GEMM == 1) src = (kt < NKX) ? (g_Xh + aX[j] + kadd) : (g_U1 + aU[j]);
            else           src = g_A2 + aX[j] + kadd;
            cp16(st + sAo[j], src);
        }
        #pragma unroll
        for (int j = 0; j < 8; j++)
            cp16(st + 16384 + sBo[j], Bb + bO[j] + kadd);
    };

    // ---- ldmatrix lane geometry ----
    int aRow[4], bRow[4];
    #pragma unroll
    for (int i = 0; i < 4; i++) aRow[i] = wm*64 + i*16 + (lane & 15);
    int aC = (lane >> 4) & 1;
    #pragma unroll
    for (int g = 0; g < 4; g++) bRow[g] = wn*64 + g*16 + (lane & 7) + ((lane & 16) ? 8 : 0);
    int bC = (lane >> 3) & 1;

    float acc[4][8][4];
    #pragma unroll
    for (int i = 0; i < 4; i++)
        #pragma unroll
        for (int j = 0; j < 8; j++)
            #pragma unroll
            for (int q = 0; q < 4; q++) acc[i][j][q] = 0.f;

    issue(0); CP_COMMIT();
    issue(1); CP_COMMIT();

    for (int kt = 0; kt < NK; kt++) {
        CP_WAIT1();
        __syncthreads();
        if (kt + 2 < NK) issue(kt + 2);
        CP_COMMIT();

        uint32_t st = sbase + (kt % 3) * STAGE;
        #pragma unroll
        for (int h = 0; h < 4; h++) {
            uint32_t ar[4][4], br[4][4];
            #pragma unroll
            for (int i = 0; i < 4; i++)
                ldsm4(ar[i], st + swz64(aRow[i], 2*h + aC));
            #pragma unroll
            for (int g = 0; g < 4; g++)
                ldsm4(br[g], st + 16384 + swz64(bRow[g], 2*h + bC));
            #pragma unroll
            for (int i = 0; i < 4; i++)
                #pragma unroll
                for (int j = 0; j < 8; j++)
                    mma_f16(acc[i][j], ar[i], &br[j>>1][(j&1)*2]);
        }
    }
    CP_WAIT0();
    __syncthreads();

    if constexpr (GEMM == 1) {
        float* ex = reinterpret_cast<float*>(smem_raw);   // [128][260] fp32 = 133120B
        #pragma unroll
        for (int i = 0; i < 4; i++)
            #pragma unroll
            for (int j = 0; j < 8; j++) {
                int r0 = wm*64 + i*16 + (lane >> 2);
                int c  = wn*64 + j*8 + (lane & 3)*2;
                ex[r0*260 + c]       = acc[i][j][0];
                ex[r0*260 + c + 1]   = acc[i][j][1];
                ex[(r0+8)*260 + c]   = acc[i][j][2];
                ex[(r0+8)*260 + c+1] = acc[i][j][3];
            }
        __syncthreads();
        int m = tid >> 1, half = tid & 1;   // 64 act cols per thread
        if (m0 + m < cnt) {
            size_t srow = (size_t)(off + m0 + m);
            float cw = tw[g_list[srow]];
            __half* da = g_A2 + srow * KT2 + blockIdx.x*128 + half*64;
            const float* gr = ex + m*260 + half*64;
            #pragma unroll
            for (int q = 0; q < 8; q++) {
                uint32_t hw[4];
                #pragma unroll
                for (int u = 0; u < 4; u++) {
                    float g0 = gr[q*8 + u*2], g1 = gr[q*8 + u*2 + 1];
                    float u0 = gr[128 + q*8 + u*2], u1 = gr[128 + q*8 + u*2 + 1];
                    float a0 = cw * u0 * g0 / (1.f + expf(-g0));
                    float a1 = cw * u1 * g1 / (1.f + expf(-g1));
                    hw[u] = pk2(__float2half(a0), __float2half(a1));
                }
                *(uint4*)(da + q*8) = make_uint4(hw[0], hw[1], hw[2], hw[3]);
            }
        }
    } else {
        int c0 = blockIdx.x * 256;
        #pragma unroll
        for (int i = 0; i < 4; i++) {
            int r0 = m0 + wm*64 + i*16 + (lane >> 2);
            #pragma unroll
            for (int j = 0; j < 8; j++) {
                int c = c0 + wn*64 + j*8 + (lane & 3)*2;
                if (r0 < cnt)
                    *(uint32_t*)(g_Dh + (size_t)(off + r0) * H_ + c) =
                        pk2(__float2half(acc[i][j][0]), __float2half(acc[i][j][1]));
                if (r0 + 8 < cnt)
                    *(uint32_t*)(g_Dh + (size_t)(off + r0 + 8) * H_ + c) =
                        pk2(__float2half(acc[i][j][2]), __float2half(acc[i][j][3]));
            }
        }
    }
}

// ============================================================
// combine: out[t] = Dh[pos(t,0)] + Dh[pos(t,1)]  (cw already folded)
// ============================================================
__global__ __launch_bounds__(256) void k_combine(float* __restrict__ out) {
    int idx = blockIdx.x * 256 + threadIdx.x;   // T_*H_/8 = 1M threads
    int t = idx >> 8, q = idx & 255;            // 8 elements per thread
    const uint4 u0 = *(const uint4*)(g_Dh + (size_t)g_pos[2*t]   * H_ + q*8);
    const uint4 u1 = *(const uint4*)(g_Dh + (size_t)g_pos[2*t+1] * H_ + q*8);
    const __half2* h0 = (const __half2*)&u0;
    const __half2* h1 = (const __half2*)&u1;
    float4 o0, o1;
    {
        float2 a = __half22float2(h0[0]), b = __half22float2(h1[0]);
        o0.x = a.x + b.x; o0.y = a.y + b.y;
        a = __half22float2(h0[1]); b = __half22float2(h1[1]);
        o0.z = a.x + b.x; o0.w = a.y + b.y;
        a = __half22float2(h0[2]); b = __half22float2(h1[2]);
        o1.x = a.x + b.x; o1.y = a.y + b.y;
        a = __half22float2(h0[3]); b = __half22float2(h1[3]);
        o1.z = a.x + b.x; o1.w = a.y + b.y;
    }
    float4* dst = (float4*)(out + (size_t)t * H_ + q*8);
    dst[0] = o0; dst[1] = o1;
}

// ============================================================
extern "C" void kernel_launch(void* const* d_in, const int* in_sizes, int n_in,
                              void* d_out, int out_size) {
    const float* x    = (const float*)d_in[0];
    const float* tw   = (const float*)d_in[1];
    const float* w13  = (const float*)d_in[2];
    const float* w2   = (const float*)d_in[3];
    const float* gu_a = (const float*)d_in[4];
    const float* gu_b = (const float*)d_in[5];
    const float* da   = (const float*)d_in[6];
    const float* db   = (const float*)d_in[7];
    const int*   ids  = (const int*)d_in[8];
    const int*   lidx = (const int*)d_in[9];
    float* out = (float*)d_out;

    cudaFuncSetAttribute(k_gemm_mma<1>, cudaFuncAttributeMaxDynamicSharedMemorySize, SMEMB);
    cudaFuncSetAttribute(k_gemm_mma<2>, cudaFuncAttributeMaxDynamicSharedMemorySize, SMEMB);

    // order chosen so k_gemm_mma<1> is launch #4 (ncu captures it)
    k_route  <<<1, 256>>>(ids, lidx);
    k_convw1 <<<E_*I2_, 256>>>(w13, gu_b);
    k_prep1  <<<P_, 256>>>(x, gu_a, ids, lidx);
    k_gemm_mma<1><<<dim3(8, 64, E_), 256, SMEMB>>>(tw);
    k_convw2 <<<E_*H_,  256>>>(w2, db);
    k_prep2  <<<P_, 256>>>(da, ids, lidx);
    k_gemm_mma<2><<<dim3(8, 64, E_), 256, SMEMB>>>(tw);
    k_combine<<<(T_*H_/8)/256, 256>>>(out);
}

// round 12
// speedup vs baseline: 2.2782x; 1.0259x over previous
#include <cuda_runtime.h>
#include <cuda_fp16.h>
#include <math.h>
#include <stdint.h>

#define E_  8
#define H_  2048
#define I_  1024
#define I2_ 2048
#define L_  4
#define R_  16
#define T_  4096
#define P_  8192

#define KT1 2112     // H + L*R  (33 * 64)
#define KT2 1088     // I + L*R  (17 * 64)

// -------- scratch (device globals; allocation-free) --------
__device__ __half g_Xh[(size_t)T_*H_];          // fp16 x, one row per token
__device__ __half g_U1[(size_t)P_*64];          // per-pair LoRA ext for GEMM1
__device__ __half g_B1[(size_t)E_*I2_*KT1];
__device__ __half g_A2[(size_t)P_*KT2];         // act (cw-scaled) + V ext
__device__ __half g_B2[(size_t)E_*H_*KT2];
__device__ __half g_Dh[(size_t)P_*H_];          // cw-scaled down output, fp16
__device__ int   g_list[P_], g_pos[P_], g_off[E_+1];

// -------- helpers --------
__device__ __forceinline__ uint32_t smem_u32(const void* p) {
    uint32_t a;
    asm("{ .reg .u64 t; cvta.to.shared.u64 t, %1; cvt.u32.u64 %0, t; }" : "=r"(a) : "l"(p));
    return a;
}
__device__ __forceinline__ uint32_t pk2(__half a, __half b) {
    __half2 t = __halves2half2(a, b);
    return *reinterpret_cast<uint32_t*>(&t);
}
__device__ __forceinline__ void cp16(uint32_t dst, const void* src) {
    asm volatile("cp.async.cg.shared.global [%0], [%1], 16;" :: "r"(dst), "l"(src));
}
#define CP_COMMIT() asm volatile("cp.async.commit_group;" ::: "memory")
#define CP_WAIT1()  asm volatile("cp.async.wait_group 1;" ::: "memory")
#define CP_WAIT0()  asm volatile("cp.async.wait_group 0;" ::: "memory")

__device__ __forceinline__ void ldsm4(uint32_t* r, uint32_t addr) {
    asm volatile("ldmatrix.sync.aligned.m8n8.x4.shared.b16 {%0,%1,%2,%3}, [%4];"
        : "=r"(r[0]), "=r"(r[1]), "=r"(r[2]), "=r"(r[3]) : "r"(addr));
}
__device__ __forceinline__ void mma_f16(float* d, const uint32_t* a, const uint32_t* b) {
    asm volatile(
        "mma.sync.aligned.m16n8k16.row.col.f32.f16.f16.f32 "
        "{%0,%1,%2,%3}, {%4,%5,%6,%7}, {%8,%9}, {%0,%1,%2,%3};"
        : "+f"(d[0]), "+f"(d[1]), "+f"(d[2]), "+f"(d[3])
        : "r"(a[0]), "r"(a[1]), "r"(a[2]), "r"(a[3]), "r"(b[0]), "r"(b[1]));
}
// [rows x 64 fp16] tile, row stride 128B, 8x 16B chunks/row
__device__ __forceinline__ uint32_t swz64(int r, int c) {
    return (uint32_t)(r * 128 + ((c ^ (r & 7)) << 4));
}

// ============================================================
// routing: sort pairs by (expert, lora)
// ============================================================
__global__ void k_route(const int* __restrict__ topk_ids,
                        const int* __restrict__ lora_idx) {
    __shared__ int cnt[E_*L_], cur[E_*L_];
    int tid = threadIdx.x;
    if (tid < E_*L_) cnt[tid] = 0;
    __syncthreads();
    for (int p = tid; p < P_; p += blockDim.x)
        atomicAdd(&cnt[topk_ids[p]*L_ + lora_idx[p>>1]], 1);
    __syncthreads();
    if (tid == 0) {
        int acc = 0;
        for (int b = 0; b < E_*L_; b++) {
            if ((b & (L_-1)) == 0) g_off[b/L_] = acc;
            cur[b] = acc; acc += cnt[b];
        }
        g_off[E_] = acc;
    }
    __syncthreads();
    for (int p = tid; p < P_; p += blockDim.x) {
        int key = topk_ids[p]*L_ + lora_idx[p>>1];
        int pos = atomicAdd(&cur[key], 1);
        g_list[pos] = p;
        g_pos[p]    = pos;
    }
}

// ============================================================
// prep1: convert x once per token (pair with even p) + U ext per pair
// ============================================================
__global__ __launch_bounds__(256) void k_prep1(
    const float* __restrict__ x, const float* __restrict__ gu_a,
    const int* __restrict__ topk_ids, const int* __restrict__ lora_idx) {
    int s = blockIdx.x, tid = threadIdx.x;
    int p = g_list[s], t = p >> 1;
    int e = topk_ids[p], l = lora_idx[t];
    const float4* x4 = (const float4*)(x + (size_t)t * H_);

    if ((p & 1) == 0) {     // convert x[t] exactly once
        float4 v0 = x4[tid*2], v1 = x4[tid*2+1];
        uint4 u;
        u.x = pk2(__float2half(v0.x), __float2half(v0.y));
        u.y = pk2(__float2half(v0.z), __float2half(v0.w));
        u.z = pk2(__float2half(v1.x), __float2half(v1.y));
        u.w = pk2(__float2half(v1.z), __float2half(v1.w));
        *(uint4*)(g_Xh + (size_t)t * H_ + tid*8) = u;
    }
    __half* ru = g_U1 + (size_t)s * 64;
    if (tid < 64) ru[tid] = __float2half(0.f);
    __syncthreads();

    int lane = tid & 31, w = tid >> 5;
    const float4* a4 = (const float4*)(gu_a + (((size_t)l*E_ + e)*R_ + w) * H_);
    const float4* b4 = a4 + (size_t)8 * (H_/4);
    float sa = 0.f, sb = 0.f;
    for (int it = lane; it < H_/4; it += 32) {
        float4 xv = x4[it], av = a4[it], bv = b4[it];
        sa += xv.x*av.x + xv.y*av.y + xv.z*av.z + xv.w*av.w;
        sb += xv.x*bv.x + xv.y*bv.y + xv.z*bv.z + xv.w*bv.w;
    }
    #pragma unroll
    for (int o = 16; o; o >>= 1) {
        sa += __shfl_down_sync(0xffffffffu, sa, o);
        sb += __shfl_down_sync(0xffffffffu, sb, o);
    }
    if (lane == 0) {
        ru[l*R_+w]   = __float2half(sa);
        ru[l*R_+w+8] = __float2half(sb);
    }
}

// ============================================================
// weight conversion (fp16)
// ============================================================
__global__ __launch_bounds__(256) void k_convw1(
    const float* __restrict__ w13, const float* __restrict__ gu_b) {
    int rc = blockIdx.x, tid = threadIdx.x;
    int e = rc >> 11, c = rc & 2047;
    const float4* src = (const float4*)(w13 + (size_t)rc * H_);
    __half* bh = g_B1 + (size_t)rc * KT1;
    float4 v0 = src[tid*2], v1 = src[tid*2+1];
    uint4 u;
    u.x = pk2(__float2half(v0.x), __float2half(v0.y));
    u.y = pk2(__float2half(v0.z), __float2half(v0.w));
    u.z = pk2(__float2half(v1.x), __float2half(v1.y));
    u.w = pk2(__float2half(v1.z), __float2half(v1.w));
    *(uint4*)(bh + tid*8) = u;
    if (tid < L_*R_) {
        int l = tid >> 4, r = tid & 15;
        bh[H_+tid] = __float2half(gu_b[(((size_t)l*E_ + e)*I2_ + c)*R_ + r]);
    }
}

__global__ __launch_bounds__(256) void k_convw2(
    const float* __restrict__ w2, const float* __restrict__ d_b) {
    int rc = blockIdx.x, tid = threadIdx.x;
    int e = rc >> 11, c = rc & 2047;
    const float4* src = (const float4*)(w2 + (size_t)rc * I_);
    __half* bh = g_B2 + (size_t)rc * KT2;
    float4 v0 = src[tid];
    *(uint2*)(bh + tid*4) = make_uint2(
        pk2(__float2half(v0.x), __float2half(v0.y)),
        pk2(__float2half(v0.z), __float2half(v0.w)));
    if (tid < L_*R_) {
        int l = tid >> 4, r = tid & 15;
        bh[I_+tid] = __float2half(d_b[(((size_t)l*E_ + e)*H_ + c)*R_ + r]);
    }
}

// ============================================================
// prep2: V = (cw*act) . d_a -> A2 ext (fp16)
// ============================================================
__global__ __launch_bounds__(256) void k_prep2(
    const float* __restrict__ d_a,
    const int* __restrict__ topk_ids, const int* __restrict__ lora_idx) {
    int s = blockIdx.x, tid = threadIdx.x;
    int p = g_list[s], t = p >> 1;
    int e = topk_ids[p], l = lora_idx[t];
    __half* ra = g_A2 + (size_t)s * KT2;
    if (tid < L_*R_) ra[I_+tid] = __float2half(0.f);
    __syncthreads();

    int lane = tid & 31, w = tid >> 5;
    const float2* a2 = (const float2*)(d_a + (((size_t)l*E_ + e)*R_ + w) * I_);
    const float2* b2 = a2 + (size_t)8 * (I_/2);
    const __half2* h2 = (const __half2*)ra;
    float sa = 0.f, sb = 0.f;
    for (int it = lane; it < I_/2; it += 32) {
        float2 fa = __half22float2(h2[it]);
        float2 av = a2[it], bv = b2[it];
        sa += fa.x*av.x + fa.y*av.y;
        sb += fa.x*bv.x + fa.y*bv.y;
    }
    #pragma unroll
    for (int o = 16; o; o >>= 1) {
        sa += __shfl_down_sync(0xffffffffu, sa, o);
        sb += __shfl_down_sync(0xffffffffu, sb, o);
    }
    if (lane == 0) {
        ra[I_+l*R_+w]   = __float2half(sa);
        ra[I_+l*R_+w+8] = __float2half(sb);
    }
}

// ============================================================
// mma.sync GEMM: CTA 128x256, 256 threads / 8 warps (64x64 each).
// Pure fp16, K chunk 64, 3 stages x 48KB (A 16KB @0, B 32KB @16384).
// GEMM1: A = g_Xh[token] (k<2048) ++ g_U1[pair]; epilogue SwiGLU*cw -> A2.
// GEMM2: A = g_A2; epilogue -> g_Dh fp16.
// ============================================================
#define STAGE 49152
#define SMEMB (3*STAGE)   // 147456 >= exchange 133120

template<int GEMM>
__global__ __launch_bounds__(256, 1) void k_gemm_mma(const float* __restrict__ tw) {
    constexpr int KTOT = (GEMM == 1) ? KT1 : KT2;
    constexpr int NK   = KTOT / 64;     // 33 / 17
    constexpr int NKX  = NK - 1;        // last kt is the LoRA-ext chunk (GEMM1)
    const __half* Bb = (GEMM == 1) ? g_B1 : g_B2;

    int e   = blockIdx.z;
    int off = g_off[e];
    int cnt = g_off[e+1] - off;
    int m0  = blockIdx.y * 128;
    if (m0 >= cnt) return;

    extern __shared__ char smem_raw[];
    uint32_t sbase = smem_u32(smem_raw);

    int tid = threadIdx.x;
    int lane = tid & 31, wid = tid >> 5;
    int wm = wid >> 2, wn = wid & 3;   // 2x4 warp grid, 64x64 each

    // ---- loader setup: A 128 rows x 8 chunks (4/thread), B 256 x 8 (8/thread) ----
    uint32_t aX[4], aU[4], sAo[4];
    #pragma unroll
    for (int j = 0; j < 4; j++) {
        int id = tid + 256*j, r = id >> 3, c = id & 7;
        int rA = m0 + r; if (rA > cnt-1) rA = cnt-1;
        int srow = off + rA;
        if (GEMM == 1) {
            int p = g_list[srow];
            aX[j] = (uint32_t)(p >> 1) * H_ + c*8;   // token x row
            aU[j] = (uint32_t)srow * 64 + c*8;       // pair ext row
        } else {
            aX[j] = (uint32_t)srow * KT2 + c*8;
        }
        sAo[j] = swz64(r, c);
    }
    uint32_t bO[8], sBo[8];
    #pragma unroll
    for (int j = 0; j < 8; j++) {
        int id = tid + 256*j, n = id >> 3, c = id & 7;
        int colB;
        if (GEMM == 1) colB = blockIdx.x*128 + (n & 127) + ((n >> 7) * I_);
        else           colB = blockIdx.x*256 + n;
        bO[j] = ((uint32_t)e * 2048 + colB) * KTOT + c*8;
        sBo[j] = swz64(n, c);
    }

    auto issue = [&](int kt) {
        uint32_t st = sbase + (kt % 3) * STAGE;
        uint32_t kadd = (uint32_t)kt * 64;
        #pragma unroll
        for (int j = 0; j < 4; j++) {
            const __half* src;
            if (GEMM == 1) src = (kt < NKX) ? (g_Xh + aX[j] + kadd) : (g_U1 + aU[j]);
            else           src = g_A2 + aX[j] + kadd;
            cp16(st + sAo[j], src);
        }
        #pragma unroll
        for (int j = 0; j < 8; j++)
            cp16(st + 16384 + sBo[j], Bb + bO[j] + kadd);
    };

    // ---- ldmatrix lane geometry ----
    int aRow[4], bRow[4];
    #pragma unroll
    for (int i = 0; i < 4; i++) aRow[i] = wm*64 + i*16 + (lane & 15);
    int aC = (lane >> 4) & 1;
    #pragma unroll
    for (int g = 0; g < 4; g++) bRow[g] = wn*64 + g*16 + (lane & 7) + ((lane & 16) ? 8 : 0);
    int bC = (lane >> 3) & 1;

    float acc[4][8][4];
    #pragma unroll
    for (int i = 0; i < 4; i++)
        #pragma unroll
        for (int j = 0; j < 8; j++)
            #pragma unroll
            for (int q = 0; q < 4; q++) acc[i][j][q] = 0.f;

    issue(0); CP_COMMIT();
    issue(1); CP_COMMIT();

    for (int kt = 0; kt < NK; kt++) {
        CP_WAIT1();
        __syncthreads();
        if (kt + 2 < NK) issue(kt + 2);
        CP_COMMIT();

        uint32_t st = sbase + (kt % 3) * STAGE;
        #pragma unroll
        for (int h = 0; h < 4; h++) {
            uint32_t ar[4][4], br[4][4];
            #pragma unroll
            for (int i = 0; i < 4; i++)
                ldsm4(ar[i], st + swz64(aRow[i], 2*h + aC));
            #pragma unroll
            for (int g = 0; g < 4; g++)
                ldsm4(br[g], st + 16384 + swz64(bRow[g], 2*h + bC));
            #pragma unroll
            for (int i = 0; i < 4; i++)
                #pragma unroll
                for (int j = 0; j < 8; j++)
                    mma_f16(acc[i][j], ar[i], &br[j>>1][(j&1)*2]);
        }
    }
    CP_WAIT0();
    __syncthreads();

    if constexpr (GEMM == 1) {
        float* ex = reinterpret_cast<float*>(smem_raw);   // [128][260] fp32 = 133120B
        #pragma unroll
        for (int i = 0; i < 4; i++)
            #pragma unroll
            for (int j = 0; j < 8; j++) {
                int r0 = wm*64 + i*16 + (lane >> 2);
                int c  = wn*64 + j*8 + (lane & 3)*2;
                ex[r0*260 + c]       = acc[i][j][0];
                ex[r0*260 + c + 1]   = acc[i][j][1];
                ex[(r0+8)*260 + c]   = acc[i][j][2];
                ex[(r0+8)*260 + c+1] = acc[i][j][3];
            }
        __syncthreads();
        int m = tid >> 1, half = tid & 1;   // 64 act cols per thread
        if (m0 + m < cnt) {
            size_t srow = (size_t)(off + m0 + m);
            float cw = tw[g_list[srow]];
            __half* da = g_A2 + srow * KT2 + blockIdx.x*128 + half*64;
            const float* gr = ex + m*260 + half*64;
            #pragma unroll
            for (int q = 0; q < 8; q++) {
                uint32_t hw[4];
                #pragma unroll
                for (int u = 0; u < 4; u++) {
                    float g0 = gr[q*8 + u*2], g1 = gr[q*8 + u*2 + 1];
                    float u0 = gr[128 + q*8 + u*2], u1 = gr[128 + q*8 + u*2 + 1];
                    float a0 = cw * u0 * g0 / (1.f + expf(-g0));
                    float a1 = cw * u1 * g1 / (1.f + expf(-g1));
                    hw[u] = pk2(__float2half(a0), __float2half(a1));
                }
                *(uint4*)(da + q*8) = make_uint4(hw[0], hw[1], hw[2], hw[3]);
            }
        }
    } else {
        int c0 = blockIdx.x * 256;
        #pragma unroll
        for (int i = 0; i < 4; i++) {
            int r0 = m0 + wm*64 + i*16 + (lane >> 2);
            #pragma unroll
            for (int j = 0; j < 8; j++) {
                int c = c0 + wn*64 + j*8 + (lane & 3)*2;
                if (r0 < cnt)
                    *(uint32_t*)(g_Dh + (size_t)(off + r0) * H_ + c) =
                        pk2(__float2half(acc[i][j][0]), __float2half(acc[i][j][1]));
                if (r0 + 8 < cnt)
                    *(uint32_t*)(g_Dh + (size_t)(off + r0 + 8) * H_ + c) =
                        pk2(__float2half(acc[i][j][2]), __float2half(acc[i][j][3]));
            }
        }
    }
}

// ============================================================
// combine: out[t] = Dh[pos(t,0)] + Dh[pos(t,1)]  (cw already folded)
// ============================================================
__global__ __launch_bounds__(256) void k_combine(float* __restrict__ out) {
    int idx = blockIdx.x * 256 + threadIdx.x;   // T_*H_/8 = 1M threads
    int t = idx >> 8, q = idx & 255;            // 8 elements per thread
    const uint4 u0 = *(const uint4*)(g_Dh + (size_t)g_pos[2*t]   * H_ + q*8);
    const uint4 u1 = *(const uint4*)(g_Dh + (size_t)g_pos[2*t+1] * H_ + q*8);
    const __half2* h0 = (const __half2*)&u0;
    const __half2* h1 = (const __half2*)&u1;
    float4 o0, o1;
    {
        float2 a = __half22float2(h0[0]), b = __half22float2(h1[0]);
        o0.x = a.x + b.x; o0.y = a.y + b.y;
        a = __half22float2(h0[1]); b = __half22float2(h1[1]);
        o0.z = a.x + b.x; o0.w = a.y + b.y;
        a = __half22float2(h0[2]); b = __half22float2(h1[2]);
        o1.x = a.x + b.x; o1.y = a.y + b.y;
        a = __half22float2(h0[3]); b = __half22float2(h1[3]);
        o1.z = a.x + b.x; o1.w = a.y + b.y;
    }
    float4* dst = (float4*)(out + (size_t)t * H_ + q*8);
    dst[0] = o0; dst[1] = o1;
}

// ============================================================
extern "C" void kernel_launch(void* const* d_in, const int* in_sizes, int n_in,
                              void* d_out, int out_size) {
    const float* x    = (const float*)d_in[0];
    const float* tw   = (const float*)d_in[1];
    const float* w13  = (const float*)d_in[2];
    const float* w2   = (const float*)d_in[3];
    const float* gu_a = (const float*)d_in[4];
    const float* gu_b = (const float*)d_in[5];
    const float* da   = (const float*)d_in[6];
    const float* db   = (const float*)d_in[7];
    const int*   ids  = (const int*)d_in[8];
    const int*   lidx = (const int*)d_in[9];
    float* out = (float*)d_out;

    // one-time resources (host objects, not device memory)
    static cudaStream_t s1 = nullptr;
    static cudaEvent_t evFork = nullptr, evW1 = nullptr, evW2 = nullptr;
    if (!s1) {
        cudaStreamCreate(&s1);
        cudaEventCreateWithFlags(&evFork, cudaEventDisableTiming);
        cudaEventCreateWithFlags(&evW1,   cudaEventDisableTiming);
        cudaEventCreateWithFlags(&evW2,   cudaEventDisableTiming);
        cudaFuncSetAttribute(k_gemm_mma<1>, cudaFuncAttributeMaxDynamicSharedMemorySize, SMEMB);
        cudaFuncSetAttribute(k_gemm_mma<2>, cudaFuncAttributeMaxDynamicSharedMemorySize, SMEMB);
    }

    // fork: weight conversion runs on s1, overlapping route/prep1 and GEMM1
    cudaEventRecord(evFork, 0);
    cudaStreamWaitEvent(s1, evFork, 0);
    k_convw1 <<<E_*I2_, 256, 0, s1>>>(w13, gu_b);
    cudaEventRecord(evW1, s1);
    k_convw2 <<<E_*H_,  256, 0, s1>>>(w2, db);
    cudaEventRecord(evW2, s1);

    // main chain
    k_route  <<<1, 256>>>(ids, lidx);
    k_prep1  <<<P_, 256>>>(x, gu_a, ids, lidx);
    cudaStreamWaitEvent(0, evW1, 0);            // B1 ready
    k_gemm_mma<1><<<dim3(8, 64, E_), 256, SMEMB>>>(tw);
    k_prep2  <<<P_, 256>>>(da, ids, lidx);
    cudaStreamWaitEvent(0, evW2, 0);            // B2 ready
    k_gemm_mma<2><<<dim3(8, 64, E_), 256, SMEMB>>>(tw);
    k_combine<<<(T_*H_/8)/256, 256>>>(out);
}

// round 13
// speedup vs baseline: 2.5818x; 1.1332x over previous
#include <cuda_runtime.h>
#include <cuda_fp16.h>
#include <math.h>
#include <stdint.h>

#define E_  8
#define H_  2048
#define I_  1024
#define I2_ 2048
#define L_  4
#define R_  16
#define T_  4096
#define P_  8192

#define KT1 2112     // H + L*R  (33 * 64)
#define KT2 1088     // I + L*R  (17 * 64)

// -------- scratch (device globals; allocation-free) --------
__device__ __half g_Xh[(size_t)T_*H_];          // fp16 x, one row per token
__device__ __half g_U1[(size_t)P_*64];          // per-pair LoRA ext for GEMM1
__device__ __half g_B1[(size_t)E_*I2_*KT1];
__device__ __half g_A2[(size_t)P_*KT2];         // act (cw-scaled) + V ext
__device__ __half g_B2[(size_t)E_*H_*KT2];
__device__ __half g_Dh[(size_t)P_*H_];          // cw-scaled down output, fp16
__device__ __half g_GAh[(size_t)L_*E_*R_*H_];   // fp16 gu_lora_a
__device__ __half g_DAh[(size_t)L_*E_*R_*I_];   // fp16 down_lora_a
__device__ int   g_list[P_], g_pos[P_], g_off[E_+1];

// -------- helpers --------
__device__ __forceinline__ uint32_t smem_u32(const void* p) {
    uint32_t a;
    asm("{ .reg .u64 t; cvta.to.shared.u64 t, %1; cvt.u32.u64 %0, t; }" : "=r"(a) : "l"(p));
    return a;
}
__device__ __forceinline__ uint32_t pk2(__half a, __half b) {
    __half2 t = __halves2half2(a, b);
    return *reinterpret_cast<uint32_t*>(&t);
}
__device__ __forceinline__ uint4 cvt8(float4 v0, float4 v1) {
    uint4 u;
    u.x = pk2(__float2half(v0.x), __float2half(v0.y));
    u.y = pk2(__float2half(v0.z), __float2half(v0.w));
    u.z = pk2(__float2half(v1.x), __float2half(v1.y));
    u.w = pk2(__float2half(v1.z), __float2half(v1.w));
    return u;
}
__device__ __forceinline__ void cp16(uint32_t dst, const void* src) {
    asm volatile("cp.async.cg.shared.global [%0], [%1], 16;" :: "r"(dst), "l"(src));
}
#define CP_COMMIT() asm volatile("cp.async.commit_group;" ::: "memory")
#define CP_WAIT1()  asm volatile("cp.async.wait_group 1;" ::: "memory")
#define CP_WAIT0()  asm volatile("cp.async.wait_group 0;" ::: "memory")

__device__ __forceinline__ void ldsm4(uint32_t* r, uint32_t addr) {
    asm volatile("ldmatrix.sync.aligned.m8n8.x4.shared.b16 {%0,%1,%2,%3}, [%4];"
        : "=r"(r[0]), "=r"(r[1]), "=r"(r[2]), "=r"(r[3]) : "r"(addr));
}
__device__ __forceinline__ void mma_f16(float* d, const uint32_t* a, const uint32_t* b) {
    asm volatile(
        "mma.sync.aligned.m16n8k16.row.col.f32.f16.f16.f32 "
        "{%0,%1,%2,%3}, {%4,%5,%6,%7}, {%8,%9}, {%0,%1,%2,%3};"
        : "+f"(d[0]), "+f"(d[1]), "+f"(d[2]), "+f"(d[3])
        : "r"(a[0]), "r"(a[1]), "r"(a[2]), "r"(a[3]), "r"(b[0]), "r"(b[1]));
}
// [rows x 64 fp16] tile, row stride 128B, 8x 16B chunks/row
__device__ __forceinline__ uint32_t swz64(int r, int c) {
    return (uint32_t)(r * 128 + ((c ^ (r & 7)) << 4));
}
__device__ __forceinline__ float wred(float v) {
    #pragma unroll
    for (int o = 16; o; o >>= 1) v += __shfl_down_sync(0xffffffffu, v, o);
    return v;
}

// ============================================================
// routing: sort pairs by (expert, lora)
// ============================================================
__global__ void k_route(const int* __restrict__ topk_ids,
                        const int* __restrict__ lora_idx) {
    __shared__ int cnt[E_*L_], cur[E_*L_];
    int tid = threadIdx.x;
    if (tid < E_*L_) cnt[tid] = 0;
    __syncthreads();
    for (int p = tid; p < P_; p += blockDim.x)
        atomicAdd(&cnt[topk_ids[p]*L_ + lora_idx[p>>1]], 1);
    __syncthreads();
    if (tid == 0) {
        int acc = 0;
        for (int b = 0; b < E_*L_; b++) {
            if ((b & (L_-1)) == 0) g_off[b/L_] = acc;
            cur[b] = acc; acc += cnt[b];
        }
        g_off[E_] = acc;
    }
    __syncthreads();
    for (int p = tid; p < P_; p += blockDim.x) {
        int key = topk_ids[p]*L_ + lora_idx[p>>1];
        int pos = atomicAdd(&cur[key], 1);
        g_list[pos] = p;
        g_pos[p]    = pos;
    }
}

// ============================================================
// conva: gu_a, d_a -> fp16 tables
// ============================================================
__global__ __launch_bounds__(256) void k_conva(
    const float* __restrict__ gu_a, const float* __restrict__ d_a) {
    int bid = blockIdx.x, tid = threadIdx.x;
    if (bid < 512) {
        size_t base = ((size_t)bid * 256 + tid) * 8;
        const float4* s = (const float4*)(gu_a + base);
        *(uint4*)(g_GAh + base) = cvt8(s[0], s[1]);
    } else {
        size_t base = ((size_t)(bid - 512) * 256 + tid) * 8;
        const float4* s = (const float4*)(d_a + base);
        *(uint4*)(g_DAh + base) = cvt8(s[0], s[1]);
    }
}

// ============================================================
// prep1: 4 sorted pairs per block. x -> smem (+ g_Xh once/token),
// U = x . gu_a (fp16 table, streamed once for all 4 pairs).
// ============================================================
__global__ __launch_bounds__(256) void k_prep1(
    const float* __restrict__ x,
    const int* __restrict__ topk_ids, const int* __restrict__ lora_idx) {
    __shared__ float sx[4][2048];
    __shared__ int sle[4], sp[4];
    int tid = threadIdx.x;
    int s0 = blockIdx.x * 4;
    if (tid < 4) {
        int p = g_list[s0 + tid];
        sp[tid] = p;
        sle[tid] = lora_idx[p >> 1] * E_ + topk_ids[p];
    }
    __syncthreads();
    #pragma unroll
    for (int j = 0; j < 4; j++) {
        int p = sp[j], t = p >> 1;
        const float4* x4 = (const float4*)(x + (size_t)t * H_);
        float4 v0 = x4[tid*2], v1 = x4[tid*2+1];
        *(float4*)&sx[j][tid*8]     = v0;
        *(float4*)&sx[j][tid*8 + 4] = v1;
        if ((p & 1) == 0)
            *(uint4*)(g_Xh + (size_t)t * H_ + tid*8) = cvt8(v0, v1);
    }
    {   // zero U rows (4 x 64)
        int j = tid >> 6, c = tid & 63;
        g_U1[(size_t)(s0 + j) * 64 + c] = __float2half(0.f);
    }
    __syncthreads();

    int lane = tid & 31, w = tid >> 5;
    bool uni = (sle[0] == sle[1]) && (sle[1] == sle[2]) && (sle[2] == sle[3]);
    if (uni) {
        const __half2* ga = (const __half2*)(g_GAh + ((size_t)sle[0]*R_ + w) * H_);
        const __half2* gb = ga + 8 * (H_/2);
        float sa[4] = {0,0,0,0}, sb[4] = {0,0,0,0};
        for (int it = lane; it < H_/2; it += 32) {
            float2 a2 = __half22float2(ga[it]);
            float2 b2 = __half22float2(gb[it]);
            #pragma unroll
            for (int j = 0; j < 4; j++) {
                float x0 = sx[j][2*it], x1 = sx[j][2*it + 1];
                sa[j] += x0*a2.x + x1*a2.y;
                sb[j] += x0*b2.x + x1*b2.y;
            }
        }
        #pragma unroll
        for (int j = 0; j < 4; j++) {
            float ra = wred(sa[j]), rb = wred(sb[j]);
            if (lane == 0) {
                int l = sle[j] / E_;
                __half* ru = g_U1 + (size_t)(s0 + j) * 64;
                ru[l*R_ + w]     = __float2half(ra);
                ru[l*R_ + w + 8] = __float2half(rb);
            }
        }
    } else {
        for (int j = 0; j < 4; j++) {
            const __half2* ga = (const __half2*)(g_GAh + ((size_t)sle[j]*R_ + w) * H_);
            const __half2* gb = ga + 8 * (H_/2);
            float sa = 0.f, sb = 0.f;
            for (int it = lane; it < H_/2; it += 32) {
                float2 a2 = __half22float2(ga[it]);
                float2 b2 = __half22float2(gb[it]);
                float x0 = sx[j][2*it], x1 = sx[j][2*it + 1];
                sa += x0*a2.x + x1*a2.y;
                sb += x0*b2.x + x1*b2.y;
            }
            sa = wred(sa); sb = wred(sb);
            if (lane == 0) {
                int l = sle[j] / E_;
                __half* ru = g_U1 + (size_t)(s0 + j) * 64;
                ru[l*R_ + w]     = __float2half(sa);
                ru[l*R_ + w + 8] = __float2half(sb);
            }
        }
    }
}

// ============================================================
// weight conversion (fp16)
// ============================================================
__global__ __launch_bounds__(256) void k_convw1(
    const float* __restrict__ w13, const float* __restrict__ gu_b) {
    int rc = blockIdx.x, tid = threadIdx.x;
    int e = rc >> 11, c = rc & 2047;
    const float4* src = (const float4*)(w13 + (size_t)rc * H_);
    __half* bh = g_B1 + (size_t)rc * KT1;
    *(uint4*)(bh + tid*8) = cvt8(src[tid*2], src[tid*2+1]);
    if (tid < L_*R_) {
        int l = tid >> 4, r = tid & 15;
        bh[H_+tid] = __float2half(gu_b[(((size_t)l*E_ + e)*I2_ + c)*R_ + r]);
    }
}

__global__ __launch_bounds__(256) void k_convw2(
    const float* __restrict__ w2, const float* __restrict__ d_b) {
    int rc = blockIdx.x, tid = threadIdx.x;
    int e = rc >> 11, c = rc & 2047;
    const float4* src = (const float4*)(w2 + (size_t)rc * I_);
    __half* bh = g_B2 + (size_t)rc * KT2;
    float4 v0 = src[tid];
    *(uint2*)(bh + tid*4) = make_uint2(
        pk2(__float2half(v0.x), __float2half(v0.y)),
        pk2(__float2half(v0.z), __float2half(v0.w)));
    if (tid < L_*R_) {
        int l = tid >> 4, r = tid & 15;
        bh[I_+tid] = __float2half(d_b[(((size_t)l*E_ + e)*H_ + c)*R_ + r]);
    }
}

// ============================================================
// prep2: 4 pairs per block. V = act . d_a (fp16 table) -> A2 ext.
// ============================================================
__global__ __launch_bounds__(256) void k_prep2(
    const int* __restrict__ topk_ids, const int* __restrict__ lora_idx) {
    __shared__ __half2 sac[4][512];   // 4 act rows, fp16
    __shared__ int sle[4];
    int tid = threadIdx.x;
    int s0 = blockIdx.x * 4;
    if (tid < 4) {
        int p = g_list[s0 + tid];
        sle[tid] = lora_idx[p >> 1] * E_ + topk_ids[p];
    }
    __syncthreads();
    #pragma unroll
    for (int j = 0; j < 4; j += 2) {   // 512 uint4 total, 256 threads x 2
        int row = j + (tid >> 7);
        int c   = tid & 127;
        const uint4 v = *(const uint4*)(g_A2 + (size_t)(s0 + row) * KT2 + c*8);
        *(uint4*)&sac[row][c*4] = v;
    }
    {   // zero ext rows
        int j = tid >> 6, c = tid & 63;
        g_A2[(size_t)(s0 + j) * KT2 + I_ + c] = __float2half(0.f);
    }
    __syncthreads();

    int lane = tid & 31, w = tid >> 5;
    bool uni = (sle[0] == sle[1]) && (sle[1] == sle[2]) && (sle[2] == sle[3]);
    if (uni) {
        const __half2* ga = (const __half2*)(g_DAh + ((size_t)sle[0]*R_ + w) * I_);
        const __half2* gb = ga + 8 * (I_/2);
        float sa[4] = {0,0,0,0}, sb[4] = {0,0,0,0};
        for (int it = lane; it < I_/2; it += 32) {
            float2 a2 = __half22float2(ga[it]);
            float2 b2 = __half22float2(gb[it]);
            #pragma unroll
            for (int j = 0; j < 4; j++) {
                float2 xv = __half22float2(sac[j][it]);
                sa[j] += xv.x*a2.x + xv.y*a2.y;
                sb[j] += xv.x*b2.x + xv.y*b2.y;
            }
        }
        #pragma unroll
        for (int j = 0; j < 4; j++) {
            float ra = wred(sa[j]), rb = wred(sb[j]);
            if (lane == 0) {
                int l = sle[j] / E_;
                __half* ru = g_A2 + (size_t)(s0 + j) * KT2 + I_;
                ru[l*R_ + w]     = __float2half(ra);
                ru[l*R_ + w + 8] = __float2half(rb);
            }
        }
    } else {
        for (int j = 0; j < 4; j++) {
            const __half2* ga = (const __half2*)(g_DAh + ((size_t)sle[j]*R_ + w) * I_);
            const __half2* gb = ga + 8 * (I_/2);
            float sa = 0.f, sb = 0.f;
            for (int it = lane; it < I_/2; it += 32) {
                float2 a2 = __half22float2(ga[it]);
                float2 b2 = __half22float2(gb[it]);
                float2 xv = __half22float2(sac[j][it]);
                sa += xv.x*a2.x + xv.y*a2.y;
                sb += xv.x*b2.x + xv.y*b2.y;
            }
            sa = wred(sa); sb = wred(sb);
            if (lane == 0) {
                int l = sle[j] / E_;
                __half* ru = g_A2 + (size_t)(s0 + j) * KT2 + I_;
                ru[l*R_ + w]     = __float2half(sa);
                ru[l*R_ + w + 8] = __float2half(sb);
            }
        }
    }
}

// ============================================================
// mma.sync GEMM: CTA 128x256, 256 threads / 8 warps (64x64 each).
// Pure fp16, K chunk 64, 3 stages x 48KB (A 16KB @0, B 32KB @16384).
// ============================================================
#define STAGE 49152
#define SMEMB (3*STAGE)   // 147456 >= exchange 133120

template<int GEMM>
__global__ __launch_bounds__(256, 1) void k_gemm_mma(const float* __restrict__ tw) {
    constexpr int KTOT = (GEMM == 1) ? KT1 : KT2;
    constexpr int NK   = KTOT / 64;
    constexpr int NKX  = NK - 1;
    const __half* Bb = (GEMM == 1) ? g_B1 : g_B2;

    int e   = blockIdx.z;
    int off = g_off[e];
    int cnt = g_off[e+1] - off;
    int m0  = blockIdx.y * 128;
    if (m0 >= cnt) return;

    extern __shared__ char smem_raw[];
    uint32_t sbase = smem_u32(smem_raw);

    int tid = threadIdx.x;
    int lane = tid & 31, wid = tid >> 5;
    int wm = wid >> 2, wn = wid & 3;

    uint32_t aX[4], aU[4], sAo[4];
    #pragma unroll
    for (int j = 0; j < 4; j++) {
        int id = tid + 256*j, r = id >> 3, c = id & 7;
        int rA = m0 + r; if (rA > cnt-1) rA = cnt-1;
        int srow = off + rA;
        if (GEMM == 1) {
            int p = g_list[srow];
            aX[j] = (uint32_t)(p >> 1) * H_ + c*8;
            aU[j] = (uint32_t)srow * 64 + c*8;
        } else {
            aX[j] = (uint32_t)srow * KT2 + c*8;
        }
        sAo[j] = swz64(r, c);
    }
    uint32_t bO[8], sBo[8];
    #pragma unroll
    for (int j = 0; j < 8; j++) {
        int id = tid + 256*j, n = id >> 3, c = id & 7;
        int colB;
        if (GEMM == 1) colB = blockIdx.x*128 + (n & 127) + ((n >> 7) * I_);
        else           colB = blockIdx.x*256 + n;
        bO[j] = ((uint32_t)e * 2048 + colB) * KTOT + c*8;
        sBo[j] = swz64(n, c);
    }

    auto issue = [&](int kt) {
        uint32_t st = sbase + (kt % 3) * STAGE;
        uint32_t kadd = (uint32_t)kt * 64;
        #pragma unroll
        for (int j = 0; j < 4; j++) {
            const __half* src;
            if (GEMM == 1) src = (kt < NKX) ? (g_Xh + aX[j] + kadd) : (g_U1 + aU[j]);
            else           src = g_A2 + aX[j] + kadd;
            cp16(st + sAo[j], src);
        }
        #pragma unroll
        for (int j = 0; j < 8; j++)
            cp16(st + 16384 + sBo[j], Bb + bO[j] + kadd);
    };

    int aRow[4], bRow[4];
    #pragma unroll
    for (int i = 0; i < 4; i++) aRow[i] = wm*64 + i*16 + (lane & 15);
    int aC = (lane >> 4) & 1;
    #pragma unroll
    for (int g = 0; g < 4; g++) bRow[g] = wn*64 + g*16 + (lane & 7) + ((lane & 16) ? 8 : 0);
    int bC = (lane >> 3) & 1;

    float acc[4][8][4];
    #pragma unroll
    for (int i = 0; i < 4; i++)
        #pragma unroll
        for (int j = 0; j < 8; j++)
            #pragma unroll
            for (int q = 0; q < 4; q++) acc[i][j][q] = 0.f;

    issue(0); CP_COMMIT();
    issue(1); CP_COMMIT();

    for (int kt = 0; kt < NK; kt++) {
        CP_WAIT1();
        __syncthreads();
        if (kt + 2 < NK) issue(kt + 2);
        CP_COMMIT();

        uint32_t st = sbase + (kt % 3) * STAGE;
        #pragma unroll
        for (int h = 0; h < 4; h++) {
            uint32_t ar[4][4], br[4][4];
            #pragma unroll
            for (int i = 0; i < 4; i++)
                ldsm4(ar[i], st + swz64(aRow[i], 2*h + aC));
            #pragma unroll
            for (int g = 0; g < 4; g++)
                ldsm4(br[g], st + 16384 + swz64(bRow[g], 2*h + bC));
            #pragma unroll
            for (int i = 0; i < 4; i++)
                #pragma unroll
                for (int j = 0; j < 8; j++)
                    mma_f16(acc[i][j], ar[i], &br[j>>1][(j&1)*2]);
        }
    }
    CP_WAIT0();
    __syncthreads();

    if constexpr (GEMM == 1) {
        float* ex = reinterpret_cast<float*>(smem_raw);
        #pragma unroll
        for (int i = 0; i < 4; i++)
            #pragma unroll
            for (int j = 0; j < 8; j++) {
                int r0 = wm*64 + i*16 + (lane >> 2);
                int c  = wn*64 + j*8 + (lane & 3)*2;
                ex[r0*260 + c]       = acc[i][j][0];
                ex[r0*260 + c + 1]   = acc[i][j][1];
                ex[(r0+8)*260 + c]   = acc[i][j][2];
                ex[(r0+8)*260 + c+1] = acc[i][j][3];
            }
        __syncthreads();
        int m = tid >> 1, half = tid & 1;
        if (m0 + m < cnt) {
            size_t srow = (size_t)(off + m0 + m);
            float cw = tw[g_list[srow]];
            __half* da = g_A2 + srow * KT2 + blockIdx.x*128 + half*64;
            const float* gr = ex + m*260 + half*64;
            #pragma unroll
            for (int q = 0; q < 8; q++) {
                uint32_t hw[4];
                #pragma unroll
                for (int u = 0; u < 4; u++) {
                    float g0 = gr[q*8 + u*2], g1 = gr[q*8 + u*2 + 1];
                    float u0 = gr[128 + q*8 + u*2], u1 = gr[128 + q*8 + u*2 + 1];
                    float a0 = cw * u0 * g0 / (1.f + expf(-g0));
                    float a1 = cw * u1 * g1 / (1.f + expf(-g1));
                    hw[u] = pk2(__float2half(a0), __float2half(a1));
                }
                *(uint4*)(da + q*8) = make_uint4(hw[0], hw[1], hw[2], hw[3]);
            }
        }
    } else {
        int c0 = blockIdx.x * 256;
        #pragma unroll
        for (int i = 0; i < 4; i++) {
            int r0 = m0 + wm*64 + i*16 + (lane >> 2);
            #pragma unroll
            for (int j = 0; j < 8; j++) {
                int c = c0 + wn*64 + j*8 + (lane & 3)*2;
                if (r0 < cnt)
                    *(uint32_t*)(g_Dh + (size_t)(off + r0) * H_ + c) =
                        pk2(__float2half(acc[i][j][0]), __float2half(acc[i][j][1]));
                if (r0 + 8 < cnt)
                    *(uint32_t*)(g_Dh + (size_t)(off + r0 + 8) * H_ + c) =
                        pk2(__float2half(acc[i][j][2]), __float2half(acc[i][j][3]));
            }
        }
    }
}

// ============================================================
// combine: out[t] = Dh[pos(t,0)] + Dh[pos(t,1)]
// ============================================================
__global__ __launch_bounds__(256) void k_combine(float* __restrict__ out) {
    int idx = blockIdx.x * 256 + threadIdx.x;
    int t = idx >> 8, q = idx & 255;
    const uint4 u0 = *(const uint4*)(g_Dh + (size_t)g_pos[2*t]   * H_ + q*8);
    const uint4 u1 = *(const uint4*)(g_Dh + (size_t)g_pos[2*t+1] * H_ + q*8);
    const __half2* h0 = (const __half2*)&u0;
    const __half2* h1 = (const __half2*)&u1;
    float4 o0, o1;
    {
        float2 a = __half22float2(h0[0]), b = __half22float2(h1[0]);
        o0.x = a.x + b.x; o0.y = a.y + b.y;
        a = __half22float2(h0[1]); b = __half22float2(h1[1]);
        o0.z = a.x + b.x; o0.w = a.y + b.y;
        a = __half22float2(h0[2]); b = __half22float2(h1[2]);
        o1.x = a.x + b.x; o1.y = a.y + b.y;
        a = __half22float2(h0[3]); b = __half22float2(h1[3]);
        o1.z = a.x + b.x; o1.w = a.y + b.y;
    }
    float4* dst = (float4*)(out + (size_t)t * H_ + q*8);
    dst[0] = o0; dst[1] = o1;
}

// ============================================================
extern "C" void kernel_launch(void* const* d_in, const int* in_sizes, int n_in,
                              void* d_out, int out_size) {
    const float* x    = (const float*)d_in[0];
    const float* tw   = (const float*)d_in[1];
    const float* w13  = (const float*)d_in[2];
    const float* w2   = (const float*)d_in[3];
    const float* gu_a = (const float*)d_in[4];
    const float* gu_b = (const float*)d_in[5];
    const float* da   = (const float*)d_in[6];
    const float* db   = (const float*)d_in[7];
    const int*   ids  = (const int*)d_in[8];
    const int*   lidx = (const int*)d_in[9];
    float* out = (float*)d_out;

    static cudaStream_t s1 = nullptr;
    static cudaEvent_t evFork = nullptr, evA = nullptr, evW1 = nullptr, evW2 = nullptr;
    if (!s1) {
        cudaStreamCreate(&s1);
        cudaEventCreateWithFlags(&evFork, cudaEventDisableTiming);
        cudaEventCreateWithFlags(&evA,    cudaEventDisableTiming);
        cudaEventCreateWithFlags(&evW1,   cudaEventDisableTiming);
        cudaEventCreateWithFlags(&evW2,   cudaEventDisableTiming);
        cudaFuncSetAttribute(k_gemm_mma<1>, cudaFuncAttributeMaxDynamicSharedMemorySize, SMEMB);
        cudaFuncSetAttribute(k_gemm_mma<2>, cudaFuncAttributeMaxDynamicSharedMemorySize, SMEMB);
    }

    // side stream: LoRA-A fp16 tables, then weight conversions
    cudaEventRecord(evFork, 0);
    cudaStreamWaitEvent(s1, evFork, 0);
    k_conva  <<<768, 256, 0, s1>>>(gu_a, da);
    cudaEventRecord(evA, s1);
    k_convw1 <<<E_*I2_, 256, 0, s1>>>(w13, gu_b);
    cudaEventRecord(evW1, s1);
    k_convw2 <<<E_*H_,  256, 0, s1>>>(w2, db);
    cudaEventRecord(evW2, s1);

    // main chain
    k_route  <<<1, 256>>>(ids, lidx);
    cudaStreamWaitEvent(0, evA, 0);             // g_GAh/g_DAh ready
    k_prep1  <<<P_/4, 256>>>(x, ids, lidx);
    cudaStreamWaitEvent(0, evW1, 0);            // B1 ready
    k_gemm_mma<1><<<dim3(8, 64, E_), 256, SMEMB>>>(tw);
    k_prep2  <<<P_/4, 256>>>(ids, lidx);
    cudaStreamWaitEvent(0, evW2, 0);            // B2 ready
    k_gemm_mma<2><<<dim3(8, 64, E_), 256, SMEMB>>>(tw);
    k_combine<<<(T_*H_/8)/256, 256>>>(out);
}